// round 1
// baseline (speedup 1.0000x reference)
#include <cuda_runtime.h>
#include <cstdint>

// Problem constants
#define BB 4
#define SS 4096
#define FF 1024
#define HH 16
#define DKk 64
#define RR 32
#define CHUNK 128
#define NCH (SS / CHUNK)   // 32
#define MM (BB * SS)       // 16384

// ---------------------------------------------------------------------------
// Scratch (device globals; no allocation allowed)
// ---------------------------------------------------------------------------
__device__ float g_q[MM * FF];   // q projection (B,S,H*DK)
__device__ float g_k[MM * FF];   // k projection
__device__ float g_x[MM * FF];   // pre-output activation (B,S,H*DK)
__device__ float g_qc[BB * NCH * FF];  // per-chunk exclusive prefix sums
__device__ float g_kc[BB * NCH * FF];

// ---------------------------------------------------------------------------
// SGEMM: C[m,n] = bias[n] + sum_k A[m,k] * Bw[n,k]
// A: MxK row-major, Bw: NxK row-major (both K-contiguous).
// BM=BN=128, BK=16, 256 threads, 8x8 per-thread microtile.
// ---------------------------------------------------------------------------
__global__ __launch_bounds__(256, 2)
void sgemm_nt_bias(const float* __restrict__ A, const float* __restrict__ Bw,
                   const float* __restrict__ bias, float* __restrict__ C,
                   int M, int N, int K)
{
    constexpr int BM = 128, BN = 128, BK = 16;
    __shared__ float As[BK][BM];
    __shared__ float Bs[BK][BN];

    const int tid = threadIdx.x;
    const int tx = tid & 15;      // 0..15 -> n microtile
    const int ty = tid >> 4;      // 0..15 -> m microtile
    const int m0 = blockIdx.y * BM;
    const int n0 = blockIdx.x * BN;

    float acc[8][8];
#pragma unroll
    for (int i = 0; i < 8; i++)
#pragma unroll
        for (int j = 0; j < 8; j++) acc[i][j] = 0.0f;

    const float* Ab = A + (size_t)m0 * K;
    const float* Bb = Bw + (size_t)n0 * K;

    for (int kt = 0; kt < K; kt += BK) {
#pragma unroll
        for (int i = 0; i < 2; i++) {
            int idx = tid + i * 256;          // 0..511
            int row = idx >> 2;               // 0..127
            int kq = (idx & 3) << 2;          // 0,4,8,12
            float4 av = *(const float4*)(Ab + (size_t)row * K + kt + kq);
            As[kq + 0][row] = av.x; As[kq + 1][row] = av.y;
            As[kq + 2][row] = av.z; As[kq + 3][row] = av.w;
            float4 bv = *(const float4*)(Bb + (size_t)row * K + kt + kq);
            Bs[kq + 0][row] = bv.x; Bs[kq + 1][row] = bv.y;
            Bs[kq + 2][row] = bv.z; Bs[kq + 3][row] = bv.w;
        }
        __syncthreads();

#pragma unroll
        for (int k = 0; k < BK; k++) {
            float4 a0 = *(const float4*)&As[k][ty * 4];
            float4 a1 = *(const float4*)&As[k][64 + ty * 4];
            float4 b0 = *(const float4*)&Bs[k][tx * 4];
            float4 b1 = *(const float4*)&Bs[k][64 + tx * 4];
            float ra[8] = {a0.x, a0.y, a0.z, a0.w, a1.x, a1.y, a1.z, a1.w};
            float rb[8] = {b0.x, b0.y, b0.z, b0.w, b1.x, b1.y, b1.z, b1.w};
#pragma unroll
            for (int i = 0; i < 8; i++)
#pragma unroll
                for (int j = 0; j < 8; j++)
                    acc[i][j] = fmaf(ra[i], rb[j], acc[i][j]);
        }
        __syncthreads();
    }

#pragma unroll
    for (int i = 0; i < 8; i++) {
        int row = m0 + ((i < 4) ? (ty * 4 + i) : (64 + ty * 4 + (i - 4)));
#pragma unroll
        for (int jg = 0; jg < 2; jg++) {
            int col = n0 + jg * 64 + tx * 4;
            float4 r;
            r.x = acc[i][jg * 4 + 0] + bias[col + 0];
            r.y = acc[i][jg * 4 + 1] + bias[col + 1];
            r.z = acc[i][jg * 4 + 2] + bias[col + 2];
            r.w = acc[i][jg * 4 + 3] + bias[col + 3];
            *(float4*)(C + (size_t)row * N + col) = r;
        }
    }
}

// ---------------------------------------------------------------------------
// Pass 1 of scan: per-column per-chunk sums of q and k projections.
// grid: (BB*NCH, FF/256), block: 256
// ---------------------------------------------------------------------------
__global__ void chunk_sums_kernel()
{
    int b = blockIdx.x / NCH;
    int ch = blockIdx.x % NCH;
    int col = blockIdx.y * 256 + threadIdx.x;
    size_t base = ((size_t)(b * SS + ch * CHUNK)) * FF + col;
    float sq = 0.f, sk = 0.f;
#pragma unroll 4
    for (int i = 0; i < CHUNK; i++) {
        sq += g_q[base + (size_t)i * FF];
        sk += g_k[base + (size_t)i * FF];
    }
    g_qc[(b * NCH + ch) * FF + col] = sq;
    g_kc[(b * NCH + ch) * FF + col] = sk;
}

// ---------------------------------------------------------------------------
// Pass 2: exclusive prefix over chunk sums. 4096 threads total.
// ---------------------------------------------------------------------------
__global__ void scan_chunks_kernel()
{
    int t = blockIdx.x * blockDim.x + threadIdx.x;   // 0..4095
    int b = t >> 10;
    int col = t & 1023;
    float aq = 0.f, ak = 0.f;
#pragma unroll
    for (int ch = 0; ch < NCH; ch++) {
        int idx = (b * NCH + ch) * FF + col;
        float tq = g_qc[idx]; g_qc[idx] = aq; aq += tq;
        float tk = g_kc[idx]; g_kc[idx] = ak; ak += tk;
    }
}

// ---------------------------------------------------------------------------
// Pass 3 (fused): in-chunk running average, l2norm, escore/rscore, Wc, write x.
// grid: BB*HH*NCH blocks, 64 threads (thread d owns dimension d of DK).
// ---------------------------------------------------------------------------
__global__ __launch_bounds__(64)
void fused_lowrank_kernel(const float* __restrict__ We, const float* __restrict__ Wr,
                          const float* __restrict__ Wc, const float* __restrict__ bc)
{
    __shared__ float sWe[DKk * RR];        // [d][e] row-major
    __shared__ float sWr[DKk * RR];
    __shared__ float sWcT[2 * RR * DKk];   // [j][d]  (transposed Wc)
    __shared__ float sbc[DKk];
    __shared__ float sqn[DKk], skn[DKk], ssc[2 * RR];
    __shared__ float red[4];

    int blk = blockIdx.x;
    int ch = blk % NCH;
    int h  = (blk / NCH) % HH;
    int b  = blk / (NCH * HH);
    int d  = threadIdx.x;

    for (int i = d; i < DKk * RR; i += 64) {
        sWe[i] = We[h * DKk * RR + i];
        sWr[i] = Wr[h * DKk * RR + i];
    }
    for (int i = d; i < 2 * RR * DKk; i += 64) {
        int j = i >> 6;          // 0..63
        int dd = i & 63;
        sWcT[i] = Wc[dd * (2 * RR) + j];
    }
    sbc[d] = bc[d];

    float qsum = g_qc[(b * NCH + ch) * FF + h * DKk + d];
    float ksum = g_kc[(b * NCH + ch) * FF + h * DKk + d];
    __syncthreads();

    int lane = d & 31, wp = d >> 5;

    for (int i = 0; i < CHUNK; i++) {
        int n = ch * CHUNK + i;
        size_t off = ((size_t)(b * SS + n)) * FF + h * DKk + d;
        qsum += g_q[off];
        ksum += g_k[off];
        float inv = 1.0f / (float)(n + 1);
        float qa = qsum * inv;
        float ka = ksum * inv;

        float vq = qa * qa, vk = ka * ka;
#pragma unroll
        for (int o = 16; o > 0; o >>= 1) {
            vq += __shfl_xor_sync(0xffffffffu, vq, o);
            vk += __shfl_xor_sync(0xffffffffu, vk, o);
        }
        if (lane == 0) { red[wp] = vq; red[2 + wp] = vk; }
        __syncthreads();

        float qn = qa / fmaxf(sqrtf(red[0] + red[1]), 1e-12f);
        float kn = ka / fmaxf(sqrtf(red[2] + red[3]), 1e-12f);
        sqn[d] = qn; skn[d] = kn;
        __syncthreads();

        float sc = 0.f;
        if (d < RR) {
#pragma unroll
            for (int dd = 0; dd < DKk; dd++) sc = fmaf(sqn[dd], sWe[dd * RR + d], sc);
        } else {
            int j = d - RR;
#pragma unroll
            for (int dd = 0; dd < DKk; dd++) sc = fmaf(skn[dd], sWr[dd * RR + j], sc);
        }
        ssc[d] = sc;
        __syncthreads();

        float x = sbc[d];
#pragma unroll
        for (int j = 0; j < 2 * RR; j++) x = fmaf(ssc[j], sWcT[j * DKk + d], x);
        g_x[off] = x;
        __syncthreads();
    }
}

// ---------------------------------------------------------------------------
// Launch
// ---------------------------------------------------------------------------
extern "C" void kernel_launch(void* const* d_in, const int* in_sizes, int n_in,
                              void* d_out, int out_size)
{
    const float* query = (const float*)d_in[0];
    const float* key   = (const float*)d_in[1];
    // d_in[2] = value (unused in p_layer branch), d_in[3] = p_layer
    const float* Wq = (const float*)d_in[4];
    const float* bq = (const float*)d_in[5];
    const float* Wk = (const float*)d_in[6];
    const float* bk = (const float*)d_in[7];
    // d_in[8] = Wv, d_in[9] = bv (unused)
    const float* We = (const float*)d_in[10];
    const float* Wr = (const float*)d_in[11];
    // d_in[12] = Lam (unused by reference)
    const float* Wc = (const float*)d_in[13];
    const float* bc = (const float*)d_in[14];
    const float* Wo = (const float*)d_in[15];
    const float* bo = (const float*)d_in[16];
    float* out = (float*)d_out;

    void *pq, *pk, *px;
    cudaGetSymbolAddress(&pq, g_q);
    cudaGetSymbolAddress(&pk, g_k);
    cudaGetSymbolAddress(&px, g_x);

    dim3 gemm_grid(FF / 128, MM / 128);   // (8, 128)

    // 1. q / k projections
    sgemm_nt_bias<<<gemm_grid, 256>>>(query, Wq, bq, (float*)pq, MM, FF, FF);
    sgemm_nt_bias<<<gemm_grid, 256>>>(key,   Wk, bk, (float*)pk, MM, FF, FF);

    // 2. chunked scan for causal running sums
    chunk_sums_kernel<<<dim3(BB * NCH, FF / 256), 256>>>();
    scan_chunks_kernel<<<16, 256>>>();

    // 3. fused: running average + l2norm + low-rank scores + Wc
    fused_lowrank_kernel<<<BB * HH * NCH, 64>>>(We, Wr, Wc, bc);

    // 4. output projection
    sgemm_nt_bias<<<gemm_grid, 256>>>((const float*)px, Wo, bo, out, MM, FF, FF);
}

// round 4
// speedup vs baseline: 1.8662x; 1.8662x over previous
#include <cuda_runtime.h>
#include <cuda_bf16.h>
#include <cstdint>

// Problem constants
#define BB 4
#define SS 4096
#define FF 1024
#define HH 16
#define DKk 64
#define RR 32
#define CHUNK 128
#define NCH (SS / CHUNK)   // 32
#define MM (BB * SS)       // 16384

// GEMM tiling
#define Bb_M 128
#define Bb_N 128
#define Bb_K 32
#define NCHUNKS (FF / Bb_K)        // 16
#define STAGE_BYTES 32768          // Ah 8K | Al 8K | Bh 8K | Bl 8K
#define NSTAGES 3
#define GEMM_SMEM (NSTAGES * STAGE_BYTES)

// ---------------------------------------------------------------------------
// Scratch (device globals; no allocation allowed)
// ---------------------------------------------------------------------------
__device__ float g_q[MM * FF];
__device__ float g_k[MM * FF];
__device__ float g_qc[BB * NCH * FF];
__device__ float g_kc[BB * NCH * FF];
__device__ __nv_bfloat16 g_qh[MM * FF], g_ql[MM * FF];
__device__ __nv_bfloat16 g_kh[MM * FF], g_kl[MM * FF];
__device__ __nv_bfloat16 g_xh[MM * FF], g_xl[MM * FF];
__device__ __nv_bfloat16 g_wqh[FF * FF], g_wql[FF * FF];
__device__ __nv_bfloat16 g_wkh[FF * FF], g_wkl[FF * FF];
__device__ __nv_bfloat16 g_woh[FF * FF], g_wol[FF * FF];

// ---------------------------------------------------------------------------
// PTX helpers (plain sm_80+ instructions only: ldmatrix / mma.sync / cp.async)
// ---------------------------------------------------------------------------
__device__ __forceinline__ uint32_t smem_u32(const void* p) {
    uint32_t a;
    asm("{ .reg .u64 t; cvta.to.shared.u64 t, %1; cvt.u32.u64 %0, t; }" : "=r"(a) : "l"(p));
    return a;
}

__device__ __forceinline__ void cpasync16(uint32_t s, const void* g) {
    asm volatile("cp.async.cg.shared.global [%0], [%1], 16;" :: "r"(s), "l"(g));
}
__device__ __forceinline__ void cp_commit() {
    asm volatile("cp.async.commit_group;" ::: "memory");
}
template <int N>
__device__ __forceinline__ void cp_wait() {
    asm volatile("cp.async.wait_group %0;" :: "n"(N) : "memory");
}

__device__ __forceinline__ void ldsm4(uint32_t* r, uint32_t addr) {
    asm volatile("ldmatrix.sync.aligned.m8n8.x4.shared.b16 {%0,%1,%2,%3}, [%4];"
                 : "=r"(r[0]), "=r"(r[1]), "=r"(r[2]), "=r"(r[3]) : "r"(addr));
}

__device__ __forceinline__ void mma16816(float* c, const uint32_t* a, const uint32_t* b) {
    asm volatile(
        "mma.sync.aligned.m16n8k16.row.col.f32.bf16.bf16.f32 "
        "{%0,%1,%2,%3}, {%4,%5,%6,%7}, {%8,%9}, {%0,%1,%2,%3};"
        : "+f"(c[0]), "+f"(c[1]), "+f"(c[2]), "+f"(c[3])
        : "r"(a[0]), "r"(a[1]), "r"(a[2]), "r"(a[3]), "r"(b[0]), "r"(b[1]));
}

// ---------------------------------------------------------------------------
// fp32 -> (bf16 hi, bf16 lo) split, vectorized
// ---------------------------------------------------------------------------
__global__ void cvt_hilo_kernel(const float* __restrict__ in,
                                __nv_bfloat16* __restrict__ hi,
                                __nv_bfloat16* __restrict__ lo, int n4)
{
    int i = blockIdx.x * blockDim.x + threadIdx.x;
    if (i >= n4) return;
    float4 v = ((const float4*)in)[i];
    __nv_bfloat16 h0 = __float2bfloat16(v.x);
    __nv_bfloat16 h1 = __float2bfloat16(v.y);
    __nv_bfloat16 h2 = __float2bfloat16(v.z);
    __nv_bfloat16 h3 = __float2bfloat16(v.w);
    __nv_bfloat16 l0 = __float2bfloat16(v.x - __bfloat162float(h0));
    __nv_bfloat16 l1 = __float2bfloat16(v.y - __bfloat162float(h1));
    __nv_bfloat16 l2 = __float2bfloat16(v.z - __bfloat162float(h2));
    __nv_bfloat16 l3 = __float2bfloat16(v.w - __bfloat162float(h3));
    ((__nv_bfloat162*)hi)[2 * i]     = __halves2bfloat162(h0, h1);
    ((__nv_bfloat162*)hi)[2 * i + 1] = __halves2bfloat162(h2, h3);
    ((__nv_bfloat162*)lo)[2 * i]     = __halves2bfloat162(l0, l1);
    ((__nv_bfloat162*)lo)[2 * i + 1] = __halves2bfloat162(l2, l3);
}

// ---------------------------------------------------------------------------
// HMMA bf16x3 GEMM: C[m,n] = bias[n] + sum_k A[m,k]*B[n,k]
// A = Ah+Al, B = Bh+Bl. 128x128 tile, K chunks of 32, 3-stage cp.async pipe.
// SMEM tile layout: 128 rows x 64B (4 x 16B segs), swizzle seg ^= (row>>1)&3.
// ---------------------------------------------------------------------------
__global__ __launch_bounds__(256, 1)
void gemm_hmma_x3(const __nv_bfloat16* __restrict__ Ah, const __nv_bfloat16* __restrict__ Al,
                  const __nv_bfloat16* __restrict__ Bh, const __nv_bfloat16* __restrict__ Bl,
                  const float* __restrict__ bias, float* __restrict__ C)
{
    extern __shared__ char smem[];
    const uint32_t sbase = smem_u32(smem);
    const int tid = threadIdx.x;
    const int wid = tid >> 5, lane = tid & 31;
    const int m0 = blockIdx.y * Bb_M;
    const int n0 = blockIdx.x * Bb_N;
    const int wm = (wid & 1) * 64;     // warp m offset within tile
    const int wn = (wid >> 1) * 32;    // warp n offset within tile

    const char* pAh = (const char*)Ah + (size_t)m0 * (FF * 2);
    const char* pAl = (const char*)Al + (size_t)m0 * (FF * 2);
    const char* pBh = (const char*)Bh + (size_t)n0 * (FF * 2);
    const char* pBl = (const char*)Bl + (size_t)n0 * (FF * 2);

    // gmem->smem load mapping (2 x 16B per thread per sub-array)
    const int lrow0 = tid >> 2;          // 0..63 (i=0) / +64 (i=1)
    const int lseg = tid & 3;

    auto load_stage = [&](int c, int buf) {
        uint32_t sb = sbase + buf * STAGE_BYTES;
        size_t kb = (size_t)c * 64;      // byte offset along K
#pragma unroll
        for (int i = 0; i < 2; i++) {
            int row = lrow0 + i * 64;
            uint32_t soff = row * 64 + ((lseg ^ ((row >> 1) & 3)) << 4);
            size_t goff = (size_t)row * (FF * 2) + kb + lseg * 16;
            cpasync16(sb + soff,         pAh + goff);
            cpasync16(sb + 8192 + soff,  pAl + goff);
            cpasync16(sb + 16384 + soff, pBh + goff);
            cpasync16(sb + 24576 + soff, pBl + goff);
        }
        cp_commit();
    };

    float acc[4][4][4];
#pragma unroll
    for (int i = 0; i < 4; i++)
#pragma unroll
        for (int j = 0; j < 4; j++)
#pragma unroll
            for (int e = 0; e < 4; e++) acc[i][j][e] = 0.0f;

    // ldmatrix address components (per warp-lane)
    // A: row = wm + mf*16 + (lane&15), seg = ks*2 + (lane>>4)
    int arow[4]; uint32_t aoffbase[4];
#pragma unroll
    for (int mf = 0; mf < 4; mf++) {
        arow[mf] = wm + mf * 16 + (lane & 15);
        aoffbase[mf] = arow[mf] * 64;
    }
    // B: row = wn + ng*16 + (lane>>4)*8 + (lane&7), seg = ks*2 + ((lane&15)>>3)
    int brow[2];
#pragma unroll
    for (int ng = 0; ng < 2; ng++)
        brow[ng] = wn + ng * 16 + ((lane >> 4) << 3) + (lane & 7);

    load_stage(0, 0);
    load_stage(1, 1);

    for (int c = 0; c < NCHUNKS; c++) {
        if (c + 1 < NCHUNKS) cp_wait<1>(); else cp_wait<0>();
        __syncthreads();
        if (c + 2 < NCHUNKS) load_stage(c + 2, (c + 2) % NSTAGES);

        uint32_t sb = sbase + (c % NSTAGES) * STAGE_BYTES;
#pragma unroll
        for (int ks = 0; ks < 2; ks++) {
            uint32_t ah[4][4], al[4][4], bh[2][4], bl[2][4];
#pragma unroll
            for (int mf = 0; mf < 4; mf++) {
                int seg = ks * 2 + (lane >> 4);
                uint32_t off = aoffbase[mf] + ((seg ^ ((arow[mf] >> 1) & 3)) << 4);
                ldsm4(ah[mf], sb + off);
                ldsm4(al[mf], sb + 8192 + off);
            }
#pragma unroll
            for (int ng = 0; ng < 2; ng++) {
                int seg = ks * 2 + ((lane & 15) >> 3);
                uint32_t off = brow[ng] * 64 + ((seg ^ ((brow[ng] >> 1) & 3)) << 4);
                ldsm4(bh[ng], sb + 16384 + off);
                ldsm4(bl[ng], sb + 24576 + off);
            }
#pragma unroll
            for (int mf = 0; mf < 4; mf++)
#pragma unroll
                for (int nf = 0; nf < 4; nf++) {
                    const uint32_t* ph = &bh[nf >> 1][(nf & 1) * 2];
                    const uint32_t* pl = &bl[nf >> 1][(nf & 1) * 2];
                    mma16816(acc[mf][nf], ah[mf], ph);
                    mma16816(acc[mf][nf], ah[mf], pl);
                    mma16816(acc[mf][nf], al[mf], ph);
                }
        }
        __syncthreads();
    }

    // Epilogue: direct float2 stores + bias
#pragma unroll
    for (int mf = 0; mf < 4; mf++) {
        int r0 = m0 + wm + mf * 16 + (lane >> 2);
#pragma unroll
        for (int nf = 0; nf < 4; nf++) {
            int col = n0 + wn + nf * 8 + (lane & 3) * 2;
            float bx = bias[col], by = bias[col + 1];
            float2 v0 = make_float2(acc[mf][nf][0] + bx, acc[mf][nf][1] + by);
            float2 v1 = make_float2(acc[mf][nf][2] + bx, acc[mf][nf][3] + by);
            *(float2*)&C[(size_t)r0 * FF + col] = v0;
            *(float2*)&C[(size_t)(r0 + 8) * FF + col] = v1;
        }
    }
}

// ---------------------------------------------------------------------------
// Pass 1 of scan: per-column per-chunk sums of q and k projections.
// ---------------------------------------------------------------------------
__global__ void chunk_sums_kernel()
{
    int b = blockIdx.x / NCH;
    int ch = blockIdx.x % NCH;
    int col = blockIdx.y * 256 + threadIdx.x;
    size_t base = ((size_t)(b * SS + ch * CHUNK)) * FF + col;
    float sq = 0.f, sk = 0.f;
#pragma unroll 4
    for (int i = 0; i < CHUNK; i++) {
        sq += g_q[base + (size_t)i * FF];
        sk += g_k[base + (size_t)i * FF];
    }
    g_qc[(b * NCH + ch) * FF + col] = sq;
    g_kc[(b * NCH + ch) * FF + col] = sk;
}

// ---------------------------------------------------------------------------
// Pass 2: exclusive prefix over chunk sums (batched loads for MLP).
// ---------------------------------------------------------------------------
__global__ void scan_chunks_kernel()
{
    int t = blockIdx.x * blockDim.x + threadIdx.x;   // 0..4095
    int b = t >> 10;
    int col = t & 1023;
    int base = (b * NCH) * FF + col;
    float vq[NCH], vk[NCH];
#pragma unroll
    for (int ch = 0; ch < NCH; ch++) {
        vq[ch] = g_qc[base + ch * FF];
        vk[ch] = g_kc[base + ch * FF];
    }
    float aq = 0.f, ak = 0.f;
#pragma unroll
    for (int ch = 0; ch < NCH; ch++) {
        float tq = vq[ch]; vq[ch] = aq; aq += tq;
        float tk = vk[ch]; vk[ch] = ak; ak += tk;
    }
#pragma unroll
    for (int ch = 0; ch < NCH; ch++) {
        g_qc[base + ch * FF] = vq[ch];
        g_kc[base + ch * FF] = vk[ch];
    }
}

// ---------------------------------------------------------------------------
// Pass 3 (fused): running average, l2norm, low-rank scores, Wc; writes hi/lo x.
// ---------------------------------------------------------------------------
__global__ __launch_bounds__(64)
void fused_lowrank_kernel(const float* __restrict__ We, const float* __restrict__ Wr,
                          const float* __restrict__ Wc, const float* __restrict__ bc)
{
    __shared__ float sWe[DKk * RR];
    __shared__ float sWr[DKk * RR];
    __shared__ float sWcT[2 * RR * DKk];
    __shared__ float sbc[DKk];
    __shared__ float sqn[DKk], skn[DKk], ssc[2 * RR];
    __shared__ float red[4];

    int blk = blockIdx.x;
    int ch = blk % NCH;
    int h  = (blk / NCH) % HH;
    int b  = blk / (NCH * HH);
    int d  = threadIdx.x;

    for (int i = d; i < DKk * RR; i += 64) {
        sWe[i] = We[h * DKk * RR + i];
        sWr[i] = Wr[h * DKk * RR + i];
    }
    for (int i = d; i < 2 * RR * DKk; i += 64) {
        int j = i >> 6;
        int dd = i & 63;
        sWcT[i] = Wc[dd * (2 * RR) + j];
    }
    sbc[d] = bc[d];

    float qsum = g_qc[(b * NCH + ch) * FF + h * DKk + d];
    float ksum = g_kc[(b * NCH + ch) * FF + h * DKk + d];
    __syncthreads();

    int lane = d & 31, wp = d >> 5;

    for (int i = 0; i < CHUNK; i++) {
        int n = ch * CHUNK + i;
        size_t off = ((size_t)(b * SS + n)) * FF + h * DKk + d;
        qsum += g_q[off];
        ksum += g_k[off];
        float inv = 1.0f / (float)(n + 1);
        float qa = qsum * inv;
        float ka = ksum * inv;

        float vq = qa * qa, vk = ka * ka;
#pragma unroll
        for (int o = 16; o > 0; o >>= 1) {
            vq += __shfl_xor_sync(0xffffffffu, vq, o);
            vk += __shfl_xor_sync(0xffffffffu, vk, o);
        }
        if (lane == 0) { red[wp] = vq; red[2 + wp] = vk; }
        __syncthreads();

        float qn = qa / fmaxf(sqrtf(red[0] + red[1]), 1e-12f);
        float kn = ka / fmaxf(sqrtf(red[2] + red[3]), 1e-12f);
        sqn[d] = qn; skn[d] = kn;
        __syncthreads();

        float sc = 0.f;
        if (d < RR) {
#pragma unroll
            for (int dd = 0; dd < DKk; dd++) sc = fmaf(sqn[dd], sWe[dd * RR + d], sc);
        } else {
            int j = d - RR;
#pragma unroll
            for (int dd = 0; dd < DKk; dd++) sc = fmaf(skn[dd], sWr[dd * RR + j], sc);
        }
        ssc[d] = sc;
        __syncthreads();

        float x = sbc[d];
#pragma unroll
        for (int j = 0; j < 2 * RR; j++) x = fmaf(ssc[j], sWcT[j * DKk + d], x);
        __nv_bfloat16 xh = __float2bfloat16(x);
        g_xh[off] = xh;
        g_xl[off] = __float2bfloat16(x - __bfloat162float(xh));
        __syncthreads();
    }
}

// ---------------------------------------------------------------------------
// Launch
// ---------------------------------------------------------------------------
extern "C" void kernel_launch(void* const* d_in, const int* in_sizes, int n_in,
                              void* d_out, int out_size)
{
    const float* query = (const float*)d_in[0];
    const float* key   = (const float*)d_in[1];
    const float* Wq = (const float*)d_in[4];
    const float* bq = (const float*)d_in[5];
    const float* Wk = (const float*)d_in[6];
    const float* bk = (const float*)d_in[7];
    const float* We = (const float*)d_in[10];
    const float* Wr = (const float*)d_in[11];
    const float* Wc = (const float*)d_in[13];
    const float* bc = (const float*)d_in[14];
    const float* Wo = (const float*)d_in[15];
    const float* bo = (const float*)d_in[16];
    float* out = (float*)d_out;

    void *pq, *pk;
    void *pqh, *pql, *pkh, *pkl, *pxh, *pxl;
    void *pwqh, *pwql, *pwkh, *pwkl, *pwoh, *pwol;
    cudaGetSymbolAddress(&pq, g_q);
    cudaGetSymbolAddress(&pk, g_k);
    cudaGetSymbolAddress(&pqh, g_qh); cudaGetSymbolAddress(&pql, g_ql);
    cudaGetSymbolAddress(&pkh, g_kh); cudaGetSymbolAddress(&pkl, g_kl);
    cudaGetSymbolAddress(&pxh, g_xh); cudaGetSymbolAddress(&pxl, g_xl);
    cudaGetSymbolAddress(&pwqh, g_wqh); cudaGetSymbolAddress(&pwql, g_wql);
    cudaGetSymbolAddress(&pwkh, g_wkh); cudaGetSymbolAddress(&pwkl, g_wkl);
    cudaGetSymbolAddress(&pwoh, g_woh); cudaGetSymbolAddress(&pwol, g_wol);

    cudaFuncSetAttribute(gemm_hmma_x3, cudaFuncAttributeMaxDynamicSharedMemorySize, GEMM_SMEM);

    // Hi/lo bf16 splits
    int n4_act = (MM * FF) / 4;
    int n4_w   = (FF * FF) / 4;
    cvt_hilo_kernel<<<(n4_act + 255) / 256, 256>>>(query, (__nv_bfloat16*)pqh, (__nv_bfloat16*)pql, n4_act);
    cvt_hilo_kernel<<<(n4_act + 255) / 256, 256>>>(key,   (__nv_bfloat16*)pkh, (__nv_bfloat16*)pkl, n4_act);
    cvt_hilo_kernel<<<(n4_w + 255) / 256, 256>>>(Wq, (__nv_bfloat16*)pwqh, (__nv_bfloat16*)pwql, n4_w);
    cvt_hilo_kernel<<<(n4_w + 255) / 256, 256>>>(Wk, (__nv_bfloat16*)pwkh, (__nv_bfloat16*)pwkl, n4_w);
    cvt_hilo_kernel<<<(n4_w + 255) / 256, 256>>>(Wo, (__nv_bfloat16*)pwoh, (__nv_bfloat16*)pwol, n4_w);

    dim3 ggrid(FF / Bb_N, MM / Bb_M);   // (8, 128)

    // 1. q / k projections (HMMA tensor cores)
    gemm_hmma_x3<<<ggrid, 256, GEMM_SMEM>>>((__nv_bfloat16*)pqh, (__nv_bfloat16*)pql,
                                            (__nv_bfloat16*)pwqh, (__nv_bfloat16*)pwql,
                                            bq, (float*)pq);
    gemm_hmma_x3<<<ggrid, 256, GEMM_SMEM>>>((__nv_bfloat16*)pkh, (__nv_bfloat16*)pkl,
                                            (__nv_bfloat16*)pwkh, (__nv_bfloat16*)pwkl,
                                            bk, (float*)pk);

    // 2. chunked scan for causal running sums
    chunk_sums_kernel<<<dim3(BB * NCH, FF / 256), 256>>>();
    scan_chunks_kernel<<<16, 256>>>();

    // 3. fused: running average + l2norm + low-rank scores + Wc (writes hi/lo x)
    fused_lowrank_kernel<<<BB * HH * NCH, 64>>>(We, Wr, Wc, bc);

    // 4. output projection (HMMA tensor cores)
    gemm_hmma_x3<<<ggrid, 256, GEMM_SMEM>>>((__nv_bfloat16*)pxh, (__nv_bfloat16*)pxl,
                                            (__nv_bfloat16*)pwoh, (__nv_bfloat16*)pwol,
                                            bo, out);
}

// round 5
// speedup vs baseline: 2.4422x; 1.3087x over previous
#include <cuda_runtime.h>
#include <cuda_fp16.h>
#include <cstdint>

// Problem constants
#define BB 4
#define SS 4096
#define FF 1024
#define HH 16
#define DKk 64
#define RR 32
#define CHUNK 128
#define NCH (SS / CHUNK)   // 32
#define MM (BB * SS)       // 16384

// GEMM tiling
#define Bb_M 128
#define Bb_N 128
#define Bb_K 32
#define NCHUNKS (FF / Bb_K)        // 16
#define STAGE_BYTES 24576          // A 8K | Bh 8K | Bl 8K
#define NSTAGES 4
#define GEMM_SMEM (NSTAGES * STAGE_BYTES)   // 96 KB

// ---------------------------------------------------------------------------
// Scratch (device globals; no allocation allowed)
// ---------------------------------------------------------------------------
__device__ float g_q[MM * FF];
__device__ float g_k[MM * FF];
__device__ float g_qc[BB * NCH * FF];
__device__ float g_kc[BB * NCH * FF];
__device__ __half g_qh[MM * FF];
__device__ __half g_kh[MM * FF];
__device__ __half g_xh[MM * FF];
__device__ __half g_wqh[FF * FF], g_wql[FF * FF];
__device__ __half g_wkh[FF * FF], g_wkl[FF * FF];
__device__ __half g_woh[FF * FF], g_wol[FF * FF];

// ---------------------------------------------------------------------------
// PTX helpers (plain sm_80+ instructions: ldmatrix / mma.sync / cp.async)
// ---------------------------------------------------------------------------
__device__ __forceinline__ uint32_t smem_u32(const void* p) {
    uint32_t a;
    asm("{ .reg .u64 t; cvta.to.shared.u64 t, %1; cvt.u32.u64 %0, t; }" : "=r"(a) : "l"(p));
    return a;
}

__device__ __forceinline__ void cpasync16(uint32_t s, const void* g) {
    asm volatile("cp.async.cg.shared.global [%0], [%1], 16;" :: "r"(s), "l"(g));
}
__device__ __forceinline__ void cp_commit() {
    asm volatile("cp.async.commit_group;" ::: "memory");
}
template <int N>
__device__ __forceinline__ void cp_wait() {
    asm volatile("cp.async.wait_group %0;" :: "n"(N) : "memory");
}

__device__ __forceinline__ void ldsm4(uint32_t* r, uint32_t addr) {
    asm volatile("ldmatrix.sync.aligned.m8n8.x4.shared.b16 {%0,%1,%2,%3}, [%4];"
                 : "=r"(r[0]), "=r"(r[1]), "=r"(r[2]), "=r"(r[3]) : "r"(addr));
}

__device__ __forceinline__ void mma16816(float* c, const uint32_t* a, const uint32_t* b) {
    asm volatile(
        "mma.sync.aligned.m16n8k16.row.col.f32.f16.f16.f32 "
        "{%0,%1,%2,%3}, {%4,%5,%6,%7}, {%8,%9}, {%0,%1,%2,%3};"
        : "+f"(c[0]), "+f"(c[1]), "+f"(c[2]), "+f"(c[3])
        : "r"(a[0]), "r"(a[1]), "r"(a[2]), "r"(a[3]), "r"(b[0]), "r"(b[1]));
}

// ---------------------------------------------------------------------------
// fp32 -> fp16 (single), vectorized
// ---------------------------------------------------------------------------
__global__ void cvt_h_kernel(const float* __restrict__ in, __half* __restrict__ out, int n4)
{
    int i = blockIdx.x * blockDim.x + threadIdx.x;
    if (i >= n4) return;
    float4 v = ((const float4*)in)[i];
    ((__half2*)out)[2 * i]     = __floats2half2_rn(v.x, v.y);
    ((__half2*)out)[2 * i + 1] = __floats2half2_rn(v.z, v.w);
}

// ---------------------------------------------------------------------------
// fp32 -> (fp16 hi, fp16 lo) split, vectorized (weights)
// ---------------------------------------------------------------------------
__global__ void cvt_hilo_kernel(const float* __restrict__ in,
                                __half* __restrict__ hi, __half* __restrict__ lo, int n4)
{
    int i = blockIdx.x * blockDim.x + threadIdx.x;
    if (i >= n4) return;
    float4 v = ((const float4*)in)[i];
    __half h0 = __float2half_rn(v.x), h1 = __float2half_rn(v.y);
    __half h2 = __float2half_rn(v.z), h3 = __float2half_rn(v.w);
    __half l0 = __float2half_rn(v.x - __half2float(h0));
    __half l1 = __float2half_rn(v.y - __half2float(h1));
    __half l2 = __float2half_rn(v.z - __half2float(h2));
    __half l3 = __float2half_rn(v.w - __half2float(h3));
    ((__half2*)hi)[2 * i]     = __halves2half2(h0, h1);
    ((__half2*)hi)[2 * i + 1] = __halves2half2(h2, h3);
    ((__half2*)lo)[2 * i]     = __halves2half2(l0, l1);
    ((__half2*)lo)[2 * i + 1] = __halves2half2(l2, l3);
}

// ---------------------------------------------------------------------------
// HMMA fp16x2 GEMM: C[m,n] = bias[n] + sum_k A[m,k]*B[n,k]
// B = Bh+Bl (hi/lo fp16 split), A single fp16. 128x128 tile, K chunks of 32,
// 4-stage cp.async pipe, 2 CTAs/SM.
// SMEM tile layout: 128 rows x 64B (4 x 16B segs), swizzle seg ^= (row>>1)&3.
// ---------------------------------------------------------------------------
__global__ __launch_bounds__(256, 2)
void gemm_hmma_x2(const __half* __restrict__ A,
                  const __half* __restrict__ Bh, const __half* __restrict__ Bl,
                  const float* __restrict__ bias, float* __restrict__ C)
{
    extern __shared__ char smem[];
    const uint32_t sbase = smem_u32(smem);
    const int tid = threadIdx.x;
    const int wid = tid >> 5, lane = tid & 31;
    const int m0 = blockIdx.y * Bb_M;
    const int n0 = blockIdx.x * Bb_N;
    const int wm = (wid & 1) * 64;     // warp m offset within tile
    const int wn = (wid >> 1) * 32;    // warp n offset within tile

    const char* pA  = (const char*)A  + (size_t)m0 * (FF * 2);
    const char* pBh = (const char*)Bh + (size_t)n0 * (FF * 2);
    const char* pBl = (const char*)Bl + (size_t)n0 * (FF * 2);

    // gmem->smem load mapping (2 x 16B per thread per sub-array)
    const int lrow0 = tid >> 2;          // 0..63 (i=0) / +64 (i=1)
    const int lseg = tid & 3;

    auto load_stage = [&](int c, int buf) {
        uint32_t sb = sbase + buf * STAGE_BYTES;
        size_t kb = (size_t)c * 64;      // byte offset along K
#pragma unroll
        for (int i = 0; i < 2; i++) {
            int row = lrow0 + i * 64;
            uint32_t soff = row * 64 + ((lseg ^ ((row >> 1) & 3)) << 4);
            size_t goff = (size_t)row * (FF * 2) + kb + lseg * 16;
            cpasync16(sb + soff,         pA + goff);
            cpasync16(sb + 8192 + soff,  pBh + goff);
            cpasync16(sb + 16384 + soff, pBl + goff);
        }
        cp_commit();
    };

    float acc[4][4][4];
#pragma unroll
    for (int i = 0; i < 4; i++)
#pragma unroll
        for (int j = 0; j < 4; j++)
#pragma unroll
            for (int e = 0; e < 4; e++) acc[i][j][e] = 0.0f;

    // ldmatrix address components (per warp-lane)
    // A: row = wm + mf*16 + (lane&15), seg = ks*2 + (lane>>4)
    int arow[4]; uint32_t aoffbase[4];
#pragma unroll
    for (int mf = 0; mf < 4; mf++) {
        arow[mf] = wm + mf * 16 + (lane & 15);
        aoffbase[mf] = arow[mf] * 64;
    }
    // B: row = wn + ng*16 + (lane>>4)*8 + (lane&7), seg = ks*2 + ((lane&15)>>3)
    int brow[2];
#pragma unroll
    for (int ng = 0; ng < 2; ng++)
        brow[ng] = wn + ng * 16 + ((lane >> 4) << 3) + (lane & 7);

    load_stage(0, 0);
    load_stage(1, 1);
    load_stage(2, 2);

    for (int c = 0; c < NCHUNKS; c++) {
        if (c + 2 < NCHUNKS) cp_wait<2>();
        else if (c + 1 < NCHUNKS) cp_wait<1>();
        else cp_wait<0>();
        __syncthreads();
        if (c + 3 < NCHUNKS) load_stage(c + 3, (c + 3) % NSTAGES);

        uint32_t sb = sbase + (c % NSTAGES) * STAGE_BYTES;
#pragma unroll
        for (int ks = 0; ks < 2; ks++) {
            uint32_t ah[4][4], bh[2][4], bl[2][4];
#pragma unroll
            for (int mf = 0; mf < 4; mf++) {
                int seg = ks * 2 + (lane >> 4);
                uint32_t off = aoffbase[mf] + ((seg ^ ((arow[mf] >> 1) & 3)) << 4);
                ldsm4(ah[mf], sb + off);
            }
#pragma unroll
            for (int ng = 0; ng < 2; ng++) {
                int seg = ks * 2 + ((lane & 15) >> 3);
                uint32_t off = brow[ng] * 64 + ((seg ^ ((brow[ng] >> 1) & 3)) << 4);
                ldsm4(bh[ng], sb + 8192 + off);
                ldsm4(bl[ng], sb + 16384 + off);
            }
#pragma unroll
            for (int mf = 0; mf < 4; mf++)
#pragma unroll
                for (int nf = 0; nf < 4; nf++) {
                    const uint32_t* ph = &bh[nf >> 1][(nf & 1) * 2];
                    const uint32_t* pl = &bl[nf >> 1][(nf & 1) * 2];
                    mma16816(acc[mf][nf], ah[mf], ph);
                    mma16816(acc[mf][nf], ah[mf], pl);
                }
        }
        __syncthreads();
    }

    // Epilogue: direct float2 stores + bias
#pragma unroll
    for (int mf = 0; mf < 4; mf++) {
        int r0 = m0 + wm + mf * 16 + (lane >> 2);
#pragma unroll
        for (int nf = 0; nf < 4; nf++) {
            int col = n0 + wn + nf * 8 + (lane & 3) * 2;
            float bx = bias[col], by = bias[col + 1];
            float2 v0 = make_float2(acc[mf][nf][0] + bx, acc[mf][nf][1] + by);
            float2 v1 = make_float2(acc[mf][nf][2] + bx, acc[mf][nf][3] + by);
            *(float2*)&C[(size_t)r0 * FF + col] = v0;
            *(float2*)&C[(size_t)(r0 + 8) * FF + col] = v1;
        }
    }
}

// ---------------------------------------------------------------------------
// Pass 1 of scan: per-column per-chunk sums of q and k projections.
// ---------------------------------------------------------------------------
__global__ void chunk_sums_kernel()
{
    int b = blockIdx.x / NCH;
    int ch = blockIdx.x % NCH;
    int col = blockIdx.y * 256 + threadIdx.x;
    size_t base = ((size_t)(b * SS + ch * CHUNK)) * FF + col;
    float sq = 0.f, sk = 0.f;
#pragma unroll 4
    for (int i = 0; i < CHUNK; i++) {
        sq += g_q[base + (size_t)i * FF];
        sk += g_k[base + (size_t)i * FF];
    }
    g_qc[(b * NCH + ch) * FF + col] = sq;
    g_kc[(b * NCH + ch) * FF + col] = sk;
}

// ---------------------------------------------------------------------------
// Pass 2: exclusive prefix over chunk sums (batched loads for MLP).
// ---------------------------------------------------------------------------
__global__ void scan_chunks_kernel()
{
    int t = blockIdx.x * blockDim.x + threadIdx.x;   // 0..4095
    int b = t >> 10;
    int col = t & 1023;
    int base = (b * NCH) * FF + col;
    float vq[NCH], vk[NCH];
#pragma unroll
    for (int ch = 0; ch < NCH; ch++) {
        vq[ch] = g_qc[base + ch * FF];
        vk[ch] = g_kc[base + ch * FF];
    }
    float aq = 0.f, ak = 0.f;
#pragma unroll
    for (int ch = 0; ch < NCH; ch++) {
        float tq = vq[ch]; vq[ch] = aq; aq += tq;
        float tk = vk[ch]; vk[ch] = ak; ak += tk;
    }
#pragma unroll
    for (int ch = 0; ch < NCH; ch++) {
        g_qc[base + ch * FF] = vq[ch];
        g_kc[base + ch * FF] = vk[ch];
    }
}

// ---------------------------------------------------------------------------
// Pass 3 (fused): running average, l2norm, low-rank scores, Wc; writes fp16 x.
// ---------------------------------------------------------------------------
__global__ __launch_bounds__(64)
void fused_lowrank_kernel(const float* __restrict__ We, const float* __restrict__ Wr,
                          const float* __restrict__ Wc, const float* __restrict__ bc)
{
    __shared__ float sWe[DKk * RR];
    __shared__ float sWr[DKk * RR];
    __shared__ float sWcT[2 * RR * DKk];
    __shared__ float sbc[DKk];
    __shared__ float sqn[DKk], skn[DKk], ssc[2 * RR];
    __shared__ float red[4];

    int blk = blockIdx.x;
    int ch = blk % NCH;
    int h  = (blk / NCH) % HH;
    int b  = blk / (NCH * HH);
    int d  = threadIdx.x;

    for (int i = d; i < DKk * RR; i += 64) {
        sWe[i] = We[h * DKk * RR + i];
        sWr[i] = Wr[h * DKk * RR + i];
    }
    for (int i = d; i < 2 * RR * DKk; i += 64) {
        int j = i >> 6;
        int dd = i & 63;
        sWcT[i] = Wc[dd * (2 * RR) + j];
    }
    sbc[d] = bc[d];

    float qsum = g_qc[(b * NCH + ch) * FF + h * DKk + d];
    float ksum = g_kc[(b * NCH + ch) * FF + h * DKk + d];
    __syncthreads();

    int lane = d & 31, wp = d >> 5;

    for (int i = 0; i < CHUNK; i++) {
        int n = ch * CHUNK + i;
        size_t off = ((size_t)(b * SS + n)) * FF + h * DKk + d;
        qsum += g_q[off];
        ksum += g_k[off];
        float inv = 1.0f / (float)(n + 1);
        float qa = qsum * inv;
        float ka = ksum * inv;

        float vq = qa * qa, vk = ka * ka;
#pragma unroll
        for (int o = 16; o > 0; o >>= 1) {
            vq += __shfl_xor_sync(0xffffffffu, vq, o);
            vk += __shfl_xor_sync(0xffffffffu, vk, o);
        }
        if (lane == 0) { red[wp] = vq; red[2 + wp] = vk; }
        __syncthreads();

        float qn = qa / fmaxf(sqrtf(red[0] + red[1]), 1e-12f);
        float kn = ka / fmaxf(sqrtf(red[2] + red[3]), 1e-12f);
        sqn[d] = qn; skn[d] = kn;
        __syncthreads();

        float sc = 0.f;
        if (d < RR) {
#pragma unroll
            for (int dd = 0; dd < DKk; dd++) sc = fmaf(sqn[dd], sWe[dd * RR + d], sc);
        } else {
            int j = d - RR;
#pragma unroll
            for (int dd = 0; dd < DKk; dd++) sc = fmaf(skn[dd], sWr[dd * RR + j], sc);
        }
        ssc[d] = sc;
        __syncthreads();

        float x = sbc[d];
#pragma unroll
        for (int j = 0; j < 2 * RR; j++) x = fmaf(ssc[j], sWcT[j * DKk + d], x);
        g_xh[off] = __float2half_rn(x);
        __syncthreads();
    }
}

// ---------------------------------------------------------------------------
// Launch
// ---------------------------------------------------------------------------
extern "C" void kernel_launch(void* const* d_in, const int* in_sizes, int n_in,
                              void* d_out, int out_size)
{
    const float* query = (const float*)d_in[0];
    const float* key   = (const float*)d_in[1];
    const float* Wq = (const float*)d_in[4];
    const float* bq = (const float*)d_in[5];
    const float* Wk = (const float*)d_in[6];
    const float* bk = (const float*)d_in[7];
    const float* We = (const float*)d_in[10];
    const float* Wr = (const float*)d_in[11];
    const float* Wc = (const float*)d_in[13];
    const float* bc = (const float*)d_in[14];
    const float* Wo = (const float*)d_in[15];
    const float* bo = (const float*)d_in[16];
    float* out = (float*)d_out;

    void *pq, *pk, *pqh, *pkh, *pxh;
    void *pwqh, *pwql, *pwkh, *pwkl, *pwoh, *pwol;
    cudaGetSymbolAddress(&pq, g_q);
    cudaGetSymbolAddress(&pk, g_k);
    cudaGetSymbolAddress(&pqh, g_qh);
    cudaGetSymbolAddress(&pkh, g_kh);
    cudaGetSymbolAddress(&pxh, g_xh);
    cudaGetSymbolAddress(&pwqh, g_wqh); cudaGetSymbolAddress(&pwql, g_wql);
    cudaGetSymbolAddress(&pwkh, g_wkh); cudaGetSymbolAddress(&pwkl, g_wkl);
    cudaGetSymbolAddress(&pwoh, g_woh); cudaGetSymbolAddress(&pwol, g_wol);

    cudaFuncSetAttribute(gemm_hmma_x2, cudaFuncAttributeMaxDynamicSharedMemorySize, GEMM_SMEM);

    // Converts: activations single fp16, weights hi/lo fp16
    int n4_act = (MM * FF) / 4;
    int n4_w   = (FF * FF) / 4;
    cvt_h_kernel<<<(n4_act + 255) / 256, 256>>>(query, (__half*)pqh, n4_act);
    cvt_h_kernel<<<(n4_act + 255) / 256, 256>>>(key,   (__half*)pkh, n4_act);
    cvt_hilo_kernel<<<(n4_w + 255) / 256, 256>>>(Wq, (__half*)pwqh, (__half*)pwql, n4_w);
    cvt_hilo_kernel<<<(n4_w + 255) / 256, 256>>>(Wk, (__half*)pwkh, (__half*)pwkl, n4_w);
    cvt_hilo_kernel<<<(n4_w + 255) / 256, 256>>>(Wo, (__half*)pwoh, (__half*)pwol, n4_w);

    dim3 ggrid(FF / Bb_N, MM / Bb_M);   // (8, 128)

    // 1. q / k projections (HMMA tensor cores)
    gemm_hmma_x2<<<ggrid, 256, GEMM_SMEM>>>((__half*)pqh, (__half*)pwqh, (__half*)pwql,
                                            bq, (float*)pq);
    gemm_hmma_x2<<<ggrid, 256, GEMM_SMEM>>>((__half*)pkh, (__half*)pwkh, (__half*)pwkl,
                                            bk, (float*)pk);

    // 2. chunked scan for causal running sums
    chunk_sums_kernel<<<dim3(BB * NCH, FF / 256), 256>>>();
    scan_chunks_kernel<<<16, 256>>>();

    // 3. fused: running average + l2norm + low-rank scores + Wc (writes fp16 x)
    fused_lowrank_kernel<<<BB * HH * NCH, 64>>>(We, Wr, Wc, bc);

    // 4. output projection (HMMA tensor cores)
    gemm_hmma_x2<<<ggrid, 256, GEMM_SMEM>>>((__half*)pxh, (__half*)pwoh, (__half*)pwol,
                                            bo, out);
}

// round 6
// speedup vs baseline: 4.8294x; 1.9775x over previous
#include <cuda_runtime.h>
#include <cuda_fp16.h>
#include <cstdint>

// Problem constants
#define BB 4
#define SS 4096
#define FF 1024
#define HH 16
#define DKk 64
#define RR 32
#define CHUNK 128
#define NCH (SS / CHUNK)   // 32
#define MM (BB * SS)       // 16384

// GEMM tiling
#define Bb_M 128
#define Bb_N 128
#define Bb_K 32
#define NCHUNKS (FF / Bb_K)        // 16
#define NSTAGES 4

// ---------------------------------------------------------------------------
// Scratch (device globals; no allocation allowed)
// ---------------------------------------------------------------------------
__device__ float g_q[MM * FF];
__device__ float g_k[MM * FF];
__device__ float g_qc[BB * NCH * FF];
__device__ float g_kc[BB * NCH * FF];
__device__ __half g_qh[MM * FF];
__device__ __half g_kh[MM * FF];
__device__ __half g_xh[MM * FF];
__device__ __half g_qn[MM * FF];
__device__ __half g_kn[MM * FF];
__device__ __half g_wqh[FF * FF];
__device__ __half g_wkh[FF * FF];
__device__ __half g_woh[FF * FF], g_wol[FF * FF];
__device__ __half g_meh[HH * DKk * DKk], g_mel[HH * DKk * DKk];
__device__ __half g_mrh[HH * DKk * DKk], g_mrl[HH * DKk * DKk];

// ---------------------------------------------------------------------------
// PTX helpers (plain sm_80+ instructions: ldmatrix / mma.sync / cp.async)
// ---------------------------------------------------------------------------
__device__ __forceinline__ uint32_t smem_u32(const void* p) {
    uint32_t a;
    asm("{ .reg .u64 t; cvta.to.shared.u64 t, %1; cvt.u32.u64 %0, t; }" : "=r"(a) : "l"(p));
    return a;
}

__device__ __forceinline__ void cpasync16(uint32_t s, const void* g) {
    asm volatile("cp.async.cg.shared.global [%0], [%1], 16;" :: "r"(s), "l"(g));
}
__device__ __forceinline__ void cp_commit() {
    asm volatile("cp.async.commit_group;" ::: "memory");
}
template <int N>
__device__ __forceinline__ void cp_wait() {
    asm volatile("cp.async.wait_group %0;" :: "n"(N) : "memory");
}

__device__ __forceinline__ void ldsm4(uint32_t* r, uint32_t addr) {
    asm volatile("ldmatrix.sync.aligned.m8n8.x4.shared.b16 {%0,%1,%2,%3}, [%4];"
                 : "=r"(r[0]), "=r"(r[1]), "=r"(r[2]), "=r"(r[3]) : "r"(addr));
}

__device__ __forceinline__ void mma16816(float* c, const uint32_t* a, const uint32_t* b) {
    asm volatile(
        "mma.sync.aligned.m16n8k16.row.col.f32.f16.f16.f32 "
        "{%0,%1,%2,%3}, {%4,%5,%6,%7}, {%8,%9}, {%0,%1,%2,%3};"
        : "+f"(c[0]), "+f"(c[1]), "+f"(c[2]), "+f"(c[3])
        : "r"(a[0]), "r"(a[1]), "r"(a[2]), "r"(a[3]), "r"(b[0]), "r"(b[1]));
}

// ---------------------------------------------------------------------------
// fp32 -> fp16 (single), vectorized
// ---------------------------------------------------------------------------
__global__ void cvt_h_kernel(const float* __restrict__ in, __half* __restrict__ out, int n4)
{
    int i = blockIdx.x * blockDim.x + threadIdx.x;
    if (i >= n4) return;
    float4 v = ((const float4*)in)[i];
    ((__half2*)out)[2 * i]     = __floats2half2_rn(v.x, v.y);
    ((__half2*)out)[2 * i + 1] = __floats2half2_rn(v.z, v.w);
}

// ---------------------------------------------------------------------------
// fp32 -> (fp16 hi, fp16 lo) split, vectorized (Wo only)
// ---------------------------------------------------------------------------
__global__ void cvt_hilo_kernel(const float* __restrict__ in,
                                __half* __restrict__ hi, __half* __restrict__ lo, int n4)
{
    int i = blockIdx.x * blockDim.x + threadIdx.x;
    if (i >= n4) return;
    float4 v = ((const float4*)in)[i];
    __half h0 = __float2half_rn(v.x), h1 = __float2half_rn(v.y);
    __half h2 = __float2half_rn(v.z), h3 = __float2half_rn(v.w);
    __half l0 = __float2half_rn(v.x - __half2float(h0));
    __half l1 = __float2half_rn(v.y - __half2float(h1));
    __half l2 = __float2half_rn(v.z - __half2float(h2));
    __half l3 = __float2half_rn(v.w - __half2float(h3));
    ((__half2*)hi)[2 * i]     = __halves2half2(h0, h1);
    ((__half2*)hi)[2 * i + 1] = __halves2half2(h2, h3);
    ((__half2*)lo)[2 * i]     = __halves2half2(l0, l1);
    ((__half2*)lo)[2 * i + 1] = __halves2half2(l2, l3);
}

// ---------------------------------------------------------------------------
// HMMA GEMM: C[m,n] = bias[n] + sum_k A[m,k]*B[n,k]
// LO=true: B = Bh+Bl (2 mma passes).  LO=false: single pass.
// 128x128 tile, K chunks of 32, 4-stage cp.async pipe, 2 CTAs/SM.
// Optional colsum: per-128-row-chunk column sums of final C (incl bias).
// ---------------------------------------------------------------------------
template <bool LO>
__global__ __launch_bounds__(256, 2)
void gemm_hmma(const __half* __restrict__ A,
               const __half* __restrict__ Bh, const __half* __restrict__ Bl,
               const float* __restrict__ bias, float* __restrict__ C,
               float* colsum)
{
    constexpr int STG = LO ? 24576 : 16384;   // A 8K | Bh 8K | (Bl 8K)
    extern __shared__ char smem[];
    __shared__ float scs[2][128];
    const uint32_t sbase = smem_u32(smem);
    const int tid = threadIdx.x;
    const int wid = tid >> 5, lane = tid & 31;
    const int m0 = blockIdx.y * Bb_M;
    const int n0 = blockIdx.x * Bb_N;
    const int wm = (wid & 1) * 64;
    const int wn = (wid >> 1) * 32;

    const char* pA  = (const char*)A  + (size_t)m0 * (FF * 2);
    const char* pBh = (const char*)Bh + (size_t)n0 * (FF * 2);
    const char* pBl = LO ? ((const char*)Bl + (size_t)n0 * (FF * 2)) : nullptr;

    const int lrow0 = tid >> 2;
    const int lseg = tid & 3;

    auto load_stage = [&](int c, int buf) {
        uint32_t sb = sbase + buf * STG;
        size_t kb = (size_t)c * 64;
#pragma unroll
        for (int i = 0; i < 2; i++) {
            int row = lrow0 + i * 64;
            uint32_t soff = row * 64 + ((lseg ^ ((row >> 1) & 3)) << 4);
            size_t goff = (size_t)row * (FF * 2) + kb + lseg * 16;
            cpasync16(sb + soff,        pA + goff);
            cpasync16(sb + 8192 + soff, pBh + goff);
            if (LO) cpasync16(sb + 16384 + soff, pBl + goff);
        }
        cp_commit();
    };

    float acc[4][4][4];
#pragma unroll
    for (int i = 0; i < 4; i++)
#pragma unroll
        for (int j = 0; j < 4; j++)
#pragma unroll
            for (int e = 0; e < 4; e++) acc[i][j][e] = 0.0f;

    int arow[4]; uint32_t aoffbase[4];
#pragma unroll
    for (int mf = 0; mf < 4; mf++) {
        arow[mf] = wm + mf * 16 + (lane & 15);
        aoffbase[mf] = arow[mf] * 64;
    }
    int brow[2];
#pragma unroll
    for (int ng = 0; ng < 2; ng++)
        brow[ng] = wn + ng * 16 + ((lane >> 4) << 3) + (lane & 7);

    load_stage(0, 0);
    load_stage(1, 1);
    load_stage(2, 2);

    for (int c = 0; c < NCHUNKS; c++) {
        if (c + 2 < NCHUNKS) cp_wait<2>();
        else if (c + 1 < NCHUNKS) cp_wait<1>();
        else cp_wait<0>();
        __syncthreads();
        if (c + 3 < NCHUNKS) load_stage(c + 3, (c + 3) % NSTAGES);

        uint32_t sb = sbase + (c % NSTAGES) * STG;
#pragma unroll
        for (int ks = 0; ks < 2; ks++) {
            uint32_t ah[4][4], bhf[2][4], blf[2][4];
#pragma unroll
            for (int mf = 0; mf < 4; mf++) {
                int seg = ks * 2 + (lane >> 4);
                uint32_t off = aoffbase[mf] + ((seg ^ ((arow[mf] >> 1) & 3)) << 4);
                ldsm4(ah[mf], sb + off);
            }
#pragma unroll
            for (int ng = 0; ng < 2; ng++) {
                int seg = ks * 2 + ((lane & 15) >> 3);
                uint32_t off = brow[ng] * 64 + ((seg ^ ((brow[ng] >> 1) & 3)) << 4);
                ldsm4(bhf[ng], sb + 8192 + off);
                if (LO) ldsm4(blf[ng], sb + 16384 + off);
            }
#pragma unroll
            for (int mf = 0; mf < 4; mf++)
#pragma unroll
                for (int nf = 0; nf < 4; nf++) {
                    const uint32_t* ph = &bhf[nf >> 1][(nf & 1) * 2];
                    mma16816(acc[mf][nf], ah[mf], ph);
                    if (LO) {
                        const uint32_t* pl = &blf[nf >> 1][(nf & 1) * 2];
                        mma16816(acc[mf][nf], ah[mf], pl);
                    }
                }
        }
        // (no trailing sync: next iteration's wait+sync orders reads before
        //  the buffer written by load_stage(c+3) is reused)
    }

    // Epilogue: direct float2 stores + bias
#pragma unroll
    for (int mf = 0; mf < 4; mf++) {
        int r0 = m0 + wm + mf * 16 + (lane >> 2);
#pragma unroll
        for (int nf = 0; nf < 4; nf++) {
            int col = n0 + wn + nf * 8 + (lane & 3) * 2;
            float bx = bias[col], by = bias[col + 1];
            float2 v0 = make_float2(acc[mf][nf][0] + bx, acc[mf][nf][1] + by);
            float2 v1 = make_float2(acc[mf][nf][2] + bx, acc[mf][nf][3] + by);
            *(float2*)&C[(size_t)r0 * FF + col] = v0;
            *(float2*)&C[(size_t)(r0 + 8) * FF + col] = v1;
        }
    }

    // Optional: per-chunk column sums (this CTA's 128 rows == one (b,chunk))
    if (colsum != nullptr) {
        float cs0[4], cs1[4];
#pragma unroll
        for (int nf = 0; nf < 4; nf++) {
            cs0[nf] = 0.f; cs1[nf] = 0.f;
#pragma unroll
            for (int mf = 0; mf < 4; mf++) {
                cs0[nf] += acc[mf][nf][0] + acc[mf][nf][2];
                cs1[nf] += acc[mf][nf][1] + acc[mf][nf][3];
            }
        }
#pragma unroll
        for (int o = 16; o >= 4; o >>= 1)
#pragma unroll
            for (int nf = 0; nf < 4; nf++) {
                cs0[nf] += __shfl_xor_sync(0xffffffffu, cs0[nf], o);
                cs1[nf] += __shfl_xor_sync(0xffffffffu, cs1[nf], o);
            }
        if (lane < 4) {
#pragma unroll
            for (int nf = 0; nf < 4; nf++) {
                scs[wid & 1][wn + nf * 8 + lane * 2]     = cs0[nf];
                scs[wid & 1][wn + nf * 8 + lane * 2 + 1] = cs1[nf];
            }
        }
        __syncthreads();
        if (tid < 128) {
            float tot = scs[0][tid] + scs[1][tid] + 128.0f * bias[n0 + tid];
            colsum[(m0 >> 7) * FF + n0 + tid] = tot;
        }
    }
}

// ---------------------------------------------------------------------------
// Exclusive prefix over per-chunk sums (batched loads for MLP).
// ---------------------------------------------------------------------------
__global__ void scan_chunks_kernel()
{
    int t = blockIdx.x * blockDim.x + threadIdx.x;   // 0..4095
    int b = t >> 10;
    int col = t & 1023;
    int base = (b * NCH) * FF + col;
    float vq[NCH], vk[NCH];
#pragma unroll
    for (int ch = 0; ch < NCH; ch++) {
        vq[ch] = g_qc[base + ch * FF];
        vk[ch] = g_kc[base + ch * FF];
    }
    float aq = 0.f, ak = 0.f;
#pragma unroll
    for (int ch = 0; ch < NCH; ch++) {
        float tq = vq[ch]; vq[ch] = aq; aq += tq;
        float tk = vk[ch]; vk[ch] = ak; ak += tk;
    }
#pragma unroll
    for (int ch = 0; ch < NCH; ch++) {
        g_qc[base + ch * FF] = vq[ch];
        g_kc[base + ch * FF] = vk[ch];
    }
}

// ---------------------------------------------------------------------------
// Scan + L2-normalize: warp per (b,h,chunk). Thread t owns dims t and t+32.
// Writes normalized qn/kn as fp16.
// ---------------------------------------------------------------------------
__global__ __launch_bounds__(256)
void norm_kernel()
{
    int gw = (blockIdx.x * blockDim.x + threadIdx.x) >> 5;   // 0..2047
    int lane = threadIdx.x & 31;
    int ch = gw & (NCH - 1);
    int h  = (gw >> 5) & (HH - 1);
    int b  = gw >> 9;

    int cb = (b * NCH + ch) * FF + h * DKk + lane;
    float q0 = g_qc[cb], q1 = g_qc[cb + 32];
    float k0 = g_kc[cb], k1 = g_kc[cb + 32];
    size_t off = ((size_t)(b * SS + ch * CHUNK)) * FF + h * DKk + lane;
    int n0 = ch * CHUNK;
    for (int i = 0; i < CHUNK; i++, off += FF) {
        q0 += g_q[off]; q1 += g_q[off + 32];
        k0 += g_k[off]; k1 += g_k[off + 32];
        float inv = 1.0f / (float)(n0 + i + 1);
        float qa0 = q0 * inv, qa1 = q1 * inv;
        float ka0 = k0 * inv, ka1 = k1 * inv;
        float nq = qa0 * qa0 + qa1 * qa1;
        float nk = ka0 * ka0 + ka1 * ka1;
#pragma unroll
        for (int o = 16; o > 0; o >>= 1) {
            nq += __shfl_xor_sync(0xffffffffu, nq, o);
            nk += __shfl_xor_sync(0xffffffffu, nk, o);
        }
        float rq = 1.0f / fmaxf(sqrtf(nq), 1e-12f);
        float rk = 1.0f / fmaxf(sqrtf(nk), 1e-12f);
        g_qn[off]      = __float2half_rn(qa0 * rq);
        g_qn[off + 32] = __float2half_rn(qa1 * rq);
        g_kn[off]      = __float2half_rn(ka0 * rk);
        g_kn[off + 32] = __float2half_rn(ka1 * rk);
    }
}

// ---------------------------------------------------------------------------
// Precompute per-head Me = We@Wc1^T, Mr = Wr@Wc2^T (stored [n][k], hi/lo fp16)
// ---------------------------------------------------------------------------
__global__ void make_m_kernel(const float* __restrict__ We, const float* __restrict__ Wr,
                              const float* __restrict__ Wc)
{
    int h = blockIdx.x;
    __shared__ float sWe[DKk * RR], sWr[DKk * RR], sWc[DKk * 2 * RR];
    for (int i = threadIdx.x; i < DKk * RR; i += 256) {
        sWe[i] = We[h * DKk * RR + i];
        sWr[i] = Wr[h * DKk * RR + i];
    }
    for (int i = threadIdx.x; i < DKk * 2 * RR; i += 256) sWc[i] = Wc[i];
    __syncthreads();
    for (int idx = threadIdx.x; idx < DKk * DKk; idx += 256) {
        int n = idx >> 6, k = idx & 63;
        float me = 0.f, mr = 0.f;
#pragma unroll
        for (int e = 0; e < RR; e++) {
            me += sWe[k * RR + e] * sWc[n * (2 * RR) + e];
            mr += sWr[k * RR + e] * sWc[n * (2 * RR) + RR + e];
        }
        __half meh = __float2half_rn(me);
        __half mrh = __float2half_rn(mr);
        g_meh[h * 4096 + idx] = meh;
        g_mel[h * 4096 + idx] = __float2half_rn(me - __half2float(meh));
        g_mrh[h * 4096 + idx] = mrh;
        g_mrl[h * 4096 + idx] = __float2half_rn(mr - __half2float(mrh));
    }
}

// ---------------------------------------------------------------------------
// x = qn@(Meh+Mel) + kn@(Mrh+Mrl) + bc, per (b,h), HMMA. Writes fp16 x.
// Tile: 128 S-rows x 64 out-cols, K=64 per operand. 128 threads.
// SMEM: sQ 16K | sK 16K | Meh 8K | Mel 8K | Mrh 8K | Mrl 8K = 64KB
// Rows are 128B (64 fp16); swizzle seg ^= row&7.
// ---------------------------------------------------------------------------
#define XG_SMEM 65536
__global__ __launch_bounds__(128)
void xgemm_kernel(const float* __restrict__ bc)
{
    extern __shared__ char smem[];
    const uint32_t sbase = smem_u32(smem);
    const int tid = threadIdx.x;
    const int wid = tid >> 5, lane = tid & 31;
    const int s0base = blockIdx.x * 128;
    const int b = blockIdx.y >> 4;
    const int h = blockIdx.y & 15;
    const int wm = wid * 32;

    // Load qn/kn tiles (128 rows x 128B each)
    {
        const char* gq = (const char*)g_qn + (((size_t)(b * SS + s0base)) * FF + h * DKk) * 2;
        const char* gk = (const char*)g_kn + (((size_t)(b * SS + s0base)) * FF + h * DKk) * 2;
        int row = tid;   // 0..127
#pragma unroll
        for (int seg = 0; seg < 8; seg++) {
            uint32_t soff = row * 128 + ((seg ^ (row & 7)) << 4);
            size_t goff = (size_t)row * (FF * 2) + seg * 16;
            cpasync16(sbase + soff,         gq + goff);
            cpasync16(sbase + 16384 + soff, gk + goff);
        }
        // M matrices: 64 rows x 128B each
        const char* srcs[4] = {(const char*)(g_meh + h * 4096), (const char*)(g_mel + h * 4096),
                               (const char*)(g_mrh + h * 4096), (const char*)(g_mrl + h * 4096)};
#pragma unroll
        for (int m = 0; m < 4; m++) {
            for (int i = tid; i < 512; i += 128) {
                int r = i >> 3, seg = i & 7;
                uint32_t soff = r * 128 + ((seg ^ (r & 7)) << 4);
                cpasync16(sbase + 32768 + m * 8192 + soff, srcs[m] + r * 128 + seg * 16);
            }
        }
        cp_commit();
    }
    cp_wait<0>();
    __syncthreads();

    float acc[2][8][4];
#pragma unroll
    for (int i = 0; i < 2; i++)
#pragma unroll
        for (int j = 0; j < 8; j++)
#pragma unroll
            for (int e = 0; e < 4; e++) acc[i][j][e] = 0.0f;

#pragma unroll
    for (int part = 0; part < 2; part++) {
        uint32_t aBase = sbase + part * 16384;
        uint32_t hBase = sbase + 32768 + part * 16384;
        uint32_t lBase = hBase + 8192;
#pragma unroll
        for (int ks = 0; ks < 4; ks++) {
            uint32_t a[2][4], bhf[4][4], blf[4][4];
#pragma unroll
            for (int mf = 0; mf < 2; mf++) {
                int arow = wm + mf * 16 + (lane & 15);
                int seg = ks * 2 + (lane >> 4);
                ldsm4(a[mf], aBase + arow * 128 + ((seg ^ (arow & 7)) << 4));
            }
#pragma unroll
            for (int ng = 0; ng < 4; ng++) {
                int brow = ng * 16 + ((lane >> 4) << 3) + (lane & 7);
                int seg = ks * 2 + ((lane & 15) >> 3);
                uint32_t off = brow * 128 + ((seg ^ (brow & 7)) << 4);
                ldsm4(bhf[ng], hBase + off);
                ldsm4(blf[ng], lBase + off);
            }
#pragma unroll
            for (int mf = 0; mf < 2; mf++)
#pragma unroll
                for (int nf = 0; nf < 8; nf++) {
                    const uint32_t* ph = &bhf[nf >> 1][(nf & 1) * 2];
                    const uint32_t* pl = &blf[nf >> 1][(nf & 1) * 2];
                    mma16816(acc[mf][nf], a[mf], ph);
                    mma16816(acc[mf][nf], a[mf], pl);
                }
        }
    }

    // Epilogue: + bc, convert fp16, store to g_xh
#pragma unroll
    for (int mf = 0; mf < 2; mf++) {
        int s0 = s0base + wm + mf * 16 + (lane >> 2);
#pragma unroll
        for (int nf = 0; nf < 8; nf++) {
            int col = nf * 8 + (lane & 3) * 2;
            float b0 = bc[col], b1 = bc[col + 1];
            size_t o0 = ((size_t)(b * SS + s0)) * FF + h * DKk + col;
            size_t o1 = o0 + (size_t)8 * FF;
            *(__half2*)&g_xh[o0] = __floats2half2_rn(acc[mf][nf][0] + b0, acc[mf][nf][1] + b1);
            *(__half2*)&g_xh[o1] = __floats2half2_rn(acc[mf][nf][2] + b0, acc[mf][nf][3] + b1);
        }
    }
}

// ---------------------------------------------------------------------------
// Launch
// ---------------------------------------------------------------------------
extern "C" void kernel_launch(void* const* d_in, const int* in_sizes, int n_in,
                              void* d_out, int out_size)
{
    const float* query = (const float*)d_in[0];
    const float* key   = (const float*)d_in[1];
    const float* Wq = (const float*)d_in[4];
    const float* bq = (const float*)d_in[5];
    const float* Wk = (const float*)d_in[6];
    const float* bk = (const float*)d_in[7];
    const float* We = (const float*)d_in[10];
    const float* Wr = (const float*)d_in[11];
    const float* Wc = (const float*)d_in[13];
    const float* bc = (const float*)d_in[14];
    const float* Wo = (const float*)d_in[15];
    const float* bo = (const float*)d_in[16];
    float* out = (float*)d_out;

    void *pq, *pk, *pqc, *pkc, *pqh, *pkh, *pxh;
    void *pwqh, *pwkh, *pwoh, *pwol;
    cudaGetSymbolAddress(&pq, g_q);
    cudaGetSymbolAddress(&pk, g_k);
    cudaGetSymbolAddress(&pqc, g_qc);
    cudaGetSymbolAddress(&pkc, g_kc);
    cudaGetSymbolAddress(&pqh, g_qh);
    cudaGetSymbolAddress(&pkh, g_kh);
    cudaGetSymbolAddress(&pxh, g_xh);
    cudaGetSymbolAddress(&pwqh, g_wqh);
    cudaGetSymbolAddress(&pwkh, g_wkh);
    cudaGetSymbolAddress(&pwoh, g_woh); cudaGetSymbolAddress(&pwol, g_wol);

    cudaFuncSetAttribute(gemm_hmma<false>, cudaFuncAttributeMaxDynamicSharedMemorySize, NSTAGES * 16384);
    cudaFuncSetAttribute(gemm_hmma<true>,  cudaFuncAttributeMaxDynamicSharedMemorySize, NSTAGES * 24576);
    cudaFuncSetAttribute(xgemm_kernel,     cudaFuncAttributeMaxDynamicSharedMemorySize, XG_SMEM);

    // Converts
    int n4_act = (MM * FF) / 4;
    int n4_w   = (FF * FF) / 4;
    cvt_h_kernel<<<(n4_act + 255) / 256, 256>>>(query, (__half*)pqh, n4_act);
    cvt_h_kernel<<<(n4_act + 255) / 256, 256>>>(key,   (__half*)pkh, n4_act);
    cvt_h_kernel<<<(n4_w + 255) / 256, 256>>>(Wq, (__half*)pwqh, n4_w);
    cvt_h_kernel<<<(n4_w + 255) / 256, 256>>>(Wk, (__half*)pwkh, n4_w);
    cvt_hilo_kernel<<<(n4_w + 255) / 256, 256>>>(Wo, (__half*)pwoh, (__half*)pwol, n4_w);
    make_m_kernel<<<HH, 256>>>(We, Wr, Wc);

    dim3 ggrid(FF / Bb_N, MM / Bb_M);   // (8, 128)

    // 1. q / k projections (single-pass fp16 HMMA) + fused chunk column sums
    gemm_hmma<false><<<ggrid, 256, NSTAGES * 16384>>>((__half*)pqh, (__half*)pwqh, nullptr,
                                                      bq, (float*)pq, (float*)pqc);
    gemm_hmma<false><<<ggrid, 256, NSTAGES * 16384>>>((__half*)pkh, (__half*)pwkh, nullptr,
                                                      bk, (float*)pk, (float*)pkc);

    // 2. exclusive scan over chunk sums
    scan_chunks_kernel<<<16, 256>>>();

    // 3. scan + l2norm -> fp16 qn/kn
    norm_kernel<<<256, 256>>>();

    // 4. x = qn@Me + kn@Mr + bc (batched HMMA)
    xgemm_kernel<<<dim3(SS / 128, BB * HH), 128, XG_SMEM>>>(bc);

    // 5. output projection (fp16x2 HMMA, hi/lo weights)
    gemm_hmma<true><<<ggrid, 256, NSTAGES * 24576>>>((__half*)pxh, (__half*)pwoh, (__half*)pwol,
                                                     bo, out, nullptr);
}

// round 7
// speedup vs baseline: 5.6046x; 1.1605x over previous
#include <cuda_runtime.h>
#include <cuda_fp16.h>
#include <cstdint>

// Problem constants
#define BB 4
#define SS 4096
#define FF 1024
#define HH 16
#define DKk 64
#define RR 32
#define CHUNK 128
#define NCH (SS / CHUNK)   // 32
#define MM (BB * SS)       // 16384

// GEMM tiling
#define Bb_M 128
#define Bb_N 128
#define NCHUNKS (FF / 32)          // 16 K-chunks of 32
#define STG 16384                  // A 8K | B 8K per stage
#define NSTAGES 4
#define GEMM_SMEM (NSTAGES * STG)  // 64 KB

// ---------------------------------------------------------------------------
// Scratch (device globals; no allocation allowed)
// ---------------------------------------------------------------------------
__device__ __half g_pq[MM * FF];   // projected q (fp16)
__device__ __half g_pk[MM * FF];   // projected k (fp16)
__device__ float g_qc[BB * NCH * FF];
__device__ float g_kc[BB * NCH * FF];
__device__ __half g_qh[MM * FF];   // fp16 query input
__device__ __half g_kh[MM * FF];   // fp16 key input
__device__ __half g_xh[MM * FF];   // pre-output activation (fp16)
__device__ __half g_qn[MM * FF];   // normalized q (fp16)
__device__ __half g_kn[MM * FF];   // normalized k (fp16)
__device__ __half g_wqh[FF * FF];
__device__ __half g_wkh[FF * FF];
__device__ __half g_woh[FF * FF];
__device__ __half g_meh[HH * DKk * DKk], g_mel[HH * DKk * DKk];
__device__ __half g_mrh[HH * DKk * DKk], g_mrl[HH * DKk * DKk];

struct GemmArgs {
    const __half* A;
    const __half* B;
    const float* bias;
    __half* Ch;     // used when HALFOUT
    float* Cf;      // used when !HALFOUT
    float* cs;      // optional per-chunk column sums
};

// ---------------------------------------------------------------------------
// PTX helpers (plain sm_80+ instructions: ldmatrix / mma.sync / cp.async)
// ---------------------------------------------------------------------------
__device__ __forceinline__ uint32_t smem_u32(const void* p) {
    uint32_t a;
    asm("{ .reg .u64 t; cvta.to.shared.u64 t, %1; cvt.u32.u64 %0, t; }" : "=r"(a) : "l"(p));
    return a;
}

__device__ __forceinline__ void cpasync16(uint32_t s, const void* g) {
    asm volatile("cp.async.cg.shared.global [%0], [%1], 16;" :: "r"(s), "l"(g));
}
__device__ __forceinline__ void cp_commit() {
    asm volatile("cp.async.commit_group;" ::: "memory");
}
template <int N>
__device__ __forceinline__ void cp_wait() {
    asm volatile("cp.async.wait_group %0;" :: "n"(N) : "memory");
}

__device__ __forceinline__ void ldsm4(uint32_t* r, uint32_t addr) {
    asm volatile("ldmatrix.sync.aligned.m8n8.x4.shared.b16 {%0,%1,%2,%3}, [%4];"
                 : "=r"(r[0]), "=r"(r[1]), "=r"(r[2]), "=r"(r[3]) : "r"(addr));
}

__device__ __forceinline__ void mma16816(float* c, const uint32_t* a, const uint32_t* b) {
    asm volatile(
        "mma.sync.aligned.m16n8k16.row.col.f32.f16.f16.f32 "
        "{%0,%1,%2,%3}, {%4,%5,%6,%7}, {%8,%9}, {%0,%1,%2,%3};"
        : "+f"(c[0]), "+f"(c[1]), "+f"(c[2]), "+f"(c[3])
        : "r"(a[0]), "r"(a[1]), "r"(a[2]), "r"(a[3]), "r"(b[0]), "r"(b[1]));
}

// ---------------------------------------------------------------------------
// fp32 -> fp16 (single), vectorized
// ---------------------------------------------------------------------------
__global__ void cvt_h_kernel(const float* __restrict__ in, __half* __restrict__ out, int n4)
{
    int i = blockIdx.x * blockDim.x + threadIdx.x;
    if (i >= n4) return;
    float4 v = ((const float4*)in)[i];
    ((__half2*)out)[2 * i]     = __floats2half2_rn(v.x, v.y);
    ((__half2*)out)[2 * i + 1] = __floats2half2_rn(v.z, v.w);
}

// ---------------------------------------------------------------------------
// HMMA GEMM: C[m,n] = bias[n] + sum_k A[m,k]*B[n,k], single fp16 pass.
// 128x128 tile, K chunks of 32, 4-stage cp.async pipe, 2 CTAs/SM.
// blockIdx.z selects arg set (fused q/k launch). HALFOUT: write fp16.
// Optional colsum: per-128-row-chunk column sums of final C (incl bias).
// ---------------------------------------------------------------------------
template <bool HALFOUT>
__global__ __launch_bounds__(256, 2)
void gemm_hmma(GemmArgs g0, GemmArgs g1)
{
    const GemmArgs g = blockIdx.z ? g1 : g0;
    extern __shared__ char smem[];
    __shared__ float scs[2][128];
    const uint32_t sbase = smem_u32(smem);
    const int tid = threadIdx.x;
    const int wid = tid >> 5, lane = tid & 31;
    const int m0 = blockIdx.y * Bb_M;
    const int n0 = blockIdx.x * Bb_N;
    const int wm = (wid & 1) * 64;
    const int wn = (wid >> 1) * 32;

    const char* pA = (const char*)g.A + (size_t)m0 * (FF * 2);
    const char* pB = (const char*)g.B + (size_t)n0 * (FF * 2);

    const int lrow0 = tid >> 2;
    const int lseg = tid & 3;

    auto load_stage = [&](int c, int buf) {
        uint32_t sb = sbase + buf * STG;
        size_t kb = (size_t)c * 64;
#pragma unroll
        for (int i = 0; i < 2; i++) {
            int row = lrow0 + i * 64;
            uint32_t soff = row * 64 + ((lseg ^ ((row >> 1) & 3)) << 4);
            size_t goff = (size_t)row * (FF * 2) + kb + lseg * 16;
            cpasync16(sb + soff,        pA + goff);
            cpasync16(sb + 8192 + soff, pB + goff);
        }
        cp_commit();
    };

    float acc[4][4][4];
#pragma unroll
    for (int i = 0; i < 4; i++)
#pragma unroll
        for (int j = 0; j < 4; j++)
#pragma unroll
            for (int e = 0; e < 4; e++) acc[i][j][e] = 0.0f;

    int arow[4]; uint32_t aoffbase[4];
#pragma unroll
    for (int mf = 0; mf < 4; mf++) {
        arow[mf] = wm + mf * 16 + (lane & 15);
        aoffbase[mf] = arow[mf] * 64;
    }
    int brow[2];
#pragma unroll
    for (int ng = 0; ng < 2; ng++)
        brow[ng] = wn + ng * 16 + ((lane >> 4) << 3) + (lane & 7);

    load_stage(0, 0);
    load_stage(1, 1);
    load_stage(2, 2);

    for (int c = 0; c < NCHUNKS; c++) {
        if (c + 2 < NCHUNKS) cp_wait<2>();
        else if (c + 1 < NCHUNKS) cp_wait<1>();
        else cp_wait<0>();
        __syncthreads();
        if (c + 3 < NCHUNKS) load_stage(c + 3, (c + 3) % NSTAGES);

        uint32_t sb = sbase + (c % NSTAGES) * STG;
#pragma unroll
        for (int ks = 0; ks < 2; ks++) {
            uint32_t ah[4][4], bf[2][4];
#pragma unroll
            for (int mf = 0; mf < 4; mf++) {
                int seg = ks * 2 + (lane >> 4);
                uint32_t off = aoffbase[mf] + ((seg ^ ((arow[mf] >> 1) & 3)) << 4);
                ldsm4(ah[mf], sb + off);
            }
#pragma unroll
            for (int ng = 0; ng < 2; ng++) {
                int seg = ks * 2 + ((lane & 15) >> 3);
                uint32_t off = brow[ng] * 64 + ((seg ^ ((brow[ng] >> 1) & 3)) << 4);
                ldsm4(bf[ng], sb + 8192 + off);
            }
#pragma unroll
            for (int mf = 0; mf < 4; mf++)
#pragma unroll
                for (int nf = 0; nf < 4; nf++)
                    mma16816(acc[mf][nf], ah[mf], &bf[nf >> 1][(nf & 1) * 2]);
        }
    }

    // Epilogue: + bias, store (fp16 or fp32)
#pragma unroll
    for (int mf = 0; mf < 4; mf++) {
        int r0 = m0 + wm + mf * 16 + (lane >> 2);
#pragma unroll
        for (int nf = 0; nf < 4; nf++) {
            int col = n0 + wn + nf * 8 + (lane & 3) * 2;
            float bx = g.bias[col], by = g.bias[col + 1];
            float v00 = acc[mf][nf][0] + bx, v01 = acc[mf][nf][1] + by;
            float v10 = acc[mf][nf][2] + bx, v11 = acc[mf][nf][3] + by;
            if (HALFOUT) {
                *(__half2*)&g.Ch[(size_t)r0 * FF + col]       = __floats2half2_rn(v00, v01);
                *(__half2*)&g.Ch[(size_t)(r0 + 8) * FF + col] = __floats2half2_rn(v10, v11);
            } else {
                *(float2*)&g.Cf[(size_t)r0 * FF + col]       = make_float2(v00, v01);
                *(float2*)&g.Cf[(size_t)(r0 + 8) * FF + col] = make_float2(v10, v11);
            }
        }
    }

    // Optional: per-chunk column sums (this CTA's 128 rows == one (b,chunk))
    if (g.cs != nullptr) {
        float cs0[4], cs1[4];
#pragma unroll
        for (int nf = 0; nf < 4; nf++) {
            cs0[nf] = 0.f; cs1[nf] = 0.f;
#pragma unroll
            for (int mf = 0; mf < 4; mf++) {
                cs0[nf] += acc[mf][nf][0] + acc[mf][nf][2];
                cs1[nf] += acc[mf][nf][1] + acc[mf][nf][3];
            }
        }
#pragma unroll
        for (int o = 16; o >= 4; o >>= 1)
#pragma unroll
            for (int nf = 0; nf < 4; nf++) {
                cs0[nf] += __shfl_xor_sync(0xffffffffu, cs0[nf], o);
                cs1[nf] += __shfl_xor_sync(0xffffffffu, cs1[nf], o);
            }
        if (lane < 4) {
#pragma unroll
            for (int nf = 0; nf < 4; nf++) {
                scs[wid & 1][wn + nf * 8 + lane * 2]     = cs0[nf];
                scs[wid & 1][wn + nf * 8 + lane * 2 + 1] = cs1[nf];
            }
        }
        __syncthreads();
        if (tid < 128) {
            float tot = scs[0][tid] + scs[1][tid] + 128.0f * g.bias[n0 + tid];
            g.cs[(m0 >> 7) * FF + n0 + tid] = tot;
        }
    }
}

// ---------------------------------------------------------------------------
// Exclusive prefix over per-chunk sums (batched loads for MLP).
// ---------------------------------------------------------------------------
__global__ void scan_chunks_kernel()
{
    int t = blockIdx.x * blockDim.x + threadIdx.x;   // 0..4095
    int b = t >> 10;
    int col = t & 1023;
    int base = (b * NCH) * FF + col;
    float vq[NCH], vk[NCH];
#pragma unroll
    for (int ch = 0; ch < NCH; ch++) {
        vq[ch] = g_qc[base + ch * FF];
        vk[ch] = g_kc[base + ch * FF];
    }
    float aq = 0.f, ak = 0.f;
#pragma unroll
    for (int ch = 0; ch < NCH; ch++) {
        float tq = vq[ch]; vq[ch] = aq; aq += tq;
        float tk = vk[ch]; vk[ch] = ak; ak += tk;
    }
#pragma unroll
    for (int ch = 0; ch < NCH; ch++) {
        g_qc[base + ch * FF] = vq[ch];
        g_kc[base + ch * FF] = vk[ch];
    }
}

// ---------------------------------------------------------------------------
// Scan + L2-normalize: warp per (b,h,chunk). Thread t owns dims 2t, 2t+1.
// Reads fp16 projected q/k; writes normalized qn/kn as fp16.
// ---------------------------------------------------------------------------
__global__ __launch_bounds__(256)
void norm_kernel()
{
    int gw = (blockIdx.x * blockDim.x + threadIdx.x) >> 5;   // 0..2047
    int lane = threadIdx.x & 31;
    int ch = gw & (NCH - 1);
    int h  = (gw >> 5) & (HH - 1);
    int b  = gw >> 9;

    int col = h * DKk + 2 * lane;
    int cb = (b * NCH + ch) * FF + col;
    float q0 = g_qc[cb], q1 = g_qc[cb + 1];
    float k0 = g_kc[cb], k1 = g_kc[cb + 1];
    size_t off = ((size_t)(b * SS + ch * CHUNK)) * FF + col;
    int n0 = ch * CHUNK;
    for (int i = 0; i < CHUNK; i++, off += FF) {
        float2 dq = __half22float2(*(const __half2*)&g_pq[off]);
        float2 dk = __half22float2(*(const __half2*)&g_pk[off]);
        q0 += dq.x; q1 += dq.y;
        k0 += dk.x; k1 += dk.y;
        float inv = 1.0f / (float)(n0 + i + 1);
        float qa0 = q0 * inv, qa1 = q1 * inv;
        float ka0 = k0 * inv, ka1 = k1 * inv;
        float nq = qa0 * qa0 + qa1 * qa1;
        float nk = ka0 * ka0 + ka1 * ka1;
#pragma unroll
        for (int o = 16; o > 0; o >>= 1) {
            nq += __shfl_xor_sync(0xffffffffu, nq, o);
            nk += __shfl_xor_sync(0xffffffffu, nk, o);
        }
        float rq = 1.0f / fmaxf(sqrtf(nq), 1e-12f);
        float rk = 1.0f / fmaxf(sqrtf(nk), 1e-12f);
        *(__half2*)&g_qn[off] = __floats2half2_rn(qa0 * rq, qa1 * rq);
        *(__half2*)&g_kn[off] = __floats2half2_rn(ka0 * rk, ka1 * rk);
    }
}

// ---------------------------------------------------------------------------
// Precompute per-head Me = We@Wc1^T, Mr = Wr@Wc2^T (stored [n][k], hi/lo fp16)
// ---------------------------------------------------------------------------
__global__ void make_m_kernel(const float* __restrict__ We, const float* __restrict__ Wr,
                              const float* __restrict__ Wc)
{
    int h = blockIdx.x;
    __shared__ float sWe[DKk * RR], sWr[DKk * RR], sWc[DKk * 2 * RR];
    for (int i = threadIdx.x; i < DKk * RR; i += 256) {
        sWe[i] = We[h * DKk * RR + i];
        sWr[i] = Wr[h * DKk * RR + i];
    }
    for (int i = threadIdx.x; i < DKk * 2 * RR; i += 256) sWc[i] = Wc[i];
    __syncthreads();
    for (int idx = threadIdx.x; idx < DKk * DKk; idx += 256) {
        int n = idx >> 6, k = idx & 63;
        float me = 0.f, mr = 0.f;
#pragma unroll
        for (int e = 0; e < RR; e++) {
            me += sWe[k * RR + e] * sWc[n * (2 * RR) + e];
            mr += sWr[k * RR + e] * sWc[n * (2 * RR) + RR + e];
        }
        __half meh = __float2half_rn(me);
        __half mrh = __float2half_rn(mr);
        g_meh[h * 4096 + idx] = meh;
        g_mel[h * 4096 + idx] = __float2half_rn(me - __half2float(meh));
        g_mrh[h * 4096 + idx] = mrh;
        g_mrl[h * 4096 + idx] = __float2half_rn(mr - __half2float(mrh));
    }
}

// ---------------------------------------------------------------------------
// x = qn@(Meh+Mel) + kn@(Mrh+Mrl) + bc, per (b,h), HMMA. Writes fp16 x.
// Tile: 128 S-rows x 64 out-cols, K=64 per operand. 128 threads.
// SMEM: sQ 16K | sK 16K | Meh 8K | Mel 8K | Mrh 8K | Mrl 8K = 64KB
// Rows are 128B (64 fp16); swizzle seg ^= row&7.
// ---------------------------------------------------------------------------
#define XG_SMEM 65536
__global__ __launch_bounds__(128)
void xgemm_kernel(const float* __restrict__ bc)
{
    extern __shared__ char smem[];
    const uint32_t sbase = smem_u32(smem);
    const int tid = threadIdx.x;
    const int wid = tid >> 5, lane = tid & 31;
    const int s0base = blockIdx.x * 128;
    const int b = blockIdx.y >> 4;
    const int h = blockIdx.y & 15;
    const int wm = wid * 32;

    {
        const char* gq = (const char*)g_qn + (((size_t)(b * SS + s0base)) * FF + h * DKk) * 2;
        const char* gk = (const char*)g_kn + (((size_t)(b * SS + s0base)) * FF + h * DKk) * 2;
        int row = tid;
#pragma unroll
        for (int seg = 0; seg < 8; seg++) {
            uint32_t soff = row * 128 + ((seg ^ (row & 7)) << 4);
            size_t goff = (size_t)row * (FF * 2) + seg * 16;
            cpasync16(sbase + soff,         gq + goff);
            cpasync16(sbase + 16384 + soff, gk + goff);
        }
        const char* srcs[4] = {(const char*)(g_meh + h * 4096), (const char*)(g_mel + h * 4096),
                               (const char*)(g_mrh + h * 4096), (const char*)(g_mrl + h * 4096)};
#pragma unroll
        for (int m = 0; m < 4; m++) {
            for (int i = tid; i < 512; i += 128) {
                int r = i >> 3, seg = i & 7;
                uint32_t soff = r * 128 + ((seg ^ (r & 7)) << 4);
                cpasync16(sbase + 32768 + m * 8192 + soff, srcs[m] + r * 128 + seg * 16);
            }
        }
        cp_commit();
    }
    cp_wait<0>();
    __syncthreads();

    float acc[2][8][4];
#pragma unroll
    for (int i = 0; i < 2; i++)
#pragma unroll
        for (int j = 0; j < 8; j++)
#pragma unroll
            for (int e = 0; e < 4; e++) acc[i][j][e] = 0.0f;

#pragma unroll
    for (int part = 0; part < 2; part++) {
        uint32_t aBase = sbase + part * 16384;
        uint32_t hBase = sbase + 32768 + part * 16384;
        uint32_t lBase = hBase + 8192;
#pragma unroll
        for (int ks = 0; ks < 4; ks++) {
            uint32_t a[2][4], bhf[4][4], blf[4][4];
#pragma unroll
            for (int mf = 0; mf < 2; mf++) {
                int arow = wm + mf * 16 + (lane & 15);
                int seg = ks * 2 + (lane >> 4);
                ldsm4(a[mf], aBase + arow * 128 + ((seg ^ (arow & 7)) << 4));
            }
#pragma unroll
            for (int ng = 0; ng < 4; ng++) {
                int brow = ng * 16 + ((lane >> 4) << 3) + (lane & 7);
                int seg = ks * 2 + ((lane & 15) >> 3);
                uint32_t off = brow * 128 + ((seg ^ (brow & 7)) << 4);
                ldsm4(bhf[ng], hBase + off);
                ldsm4(blf[ng], lBase + off);
            }
#pragma unroll
            for (int mf = 0; mf < 2; mf++)
#pragma unroll
                for (int nf = 0; nf < 8; nf++) {
                    mma16816(acc[mf][nf], a[mf], &bhf[nf >> 1][(nf & 1) * 2]);
                    mma16816(acc[mf][nf], a[mf], &blf[nf >> 1][(nf & 1) * 2]);
                }
        }
    }

#pragma unroll
    for (int mf = 0; mf < 2; mf++) {
        int s0 = s0base + wm + mf * 16 + (lane >> 2);
#pragma unroll
        for (int nf = 0; nf < 8; nf++) {
            int col = nf * 8 + (lane & 3) * 2;
            float b0 = bc[col], b1 = bc[col + 1];
            size_t o0 = ((size_t)(b * SS + s0)) * FF + h * DKk + col;
            size_t o1 = o0 + (size_t)8 * FF;
            *(__half2*)&g_xh[o0] = __floats2half2_rn(acc[mf][nf][0] + b0, acc[mf][nf][1] + b1);
            *(__half2*)&g_xh[o1] = __floats2half2_rn(acc[mf][nf][2] + b0, acc[mf][nf][3] + b1);
        }
    }
}

// ---------------------------------------------------------------------------
// Launch
// ---------------------------------------------------------------------------
extern "C" void kernel_launch(void* const* d_in, const int* in_sizes, int n_in,
                              void* d_out, int out_size)
{
    const float* query = (const float*)d_in[0];
    const float* key   = (const float*)d_in[1];
    const float* Wq = (const float*)d_in[4];
    const float* bq = (const float*)d_in[5];
    const float* Wk = (const float*)d_in[6];
    const float* bk = (const float*)d_in[7];
    const float* We = (const float*)d_in[10];
    const float* Wr = (const float*)d_in[11];
    const float* Wc = (const float*)d_in[13];
    const float* bc = (const float*)d_in[14];
    const float* Wo = (const float*)d_in[15];
    const float* bo = (const float*)d_in[16];
    float* out = (float*)d_out;

    void *ppq, *ppk, *pqc, *pkc, *pqh, *pkh, *pxh;
    void *pwqh, *pwkh, *pwoh;
    cudaGetSymbolAddress(&ppq, g_pq);
    cudaGetSymbolAddress(&ppk, g_pk);
    cudaGetSymbolAddress(&pqc, g_qc);
    cudaGetSymbolAddress(&pkc, g_kc);
    cudaGetSymbolAddress(&pqh, g_qh);
    cudaGetSymbolAddress(&pkh, g_kh);
    cudaGetSymbolAddress(&pxh, g_xh);
    cudaGetSymbolAddress(&pwqh, g_wqh);
    cudaGetSymbolAddress(&pwkh, g_wkh);
    cudaGetSymbolAddress(&pwoh, g_woh);

    cudaFuncSetAttribute(gemm_hmma<true>,  cudaFuncAttributeMaxDynamicSharedMemorySize, GEMM_SMEM);
    cudaFuncSetAttribute(gemm_hmma<false>, cudaFuncAttributeMaxDynamicSharedMemorySize, GEMM_SMEM);
    cudaFuncSetAttribute(xgemm_kernel,     cudaFuncAttributeMaxDynamicSharedMemorySize, XG_SMEM);

    // Converts (all single fp16)
    int n4_act = (MM * FF) / 4;
    int n4_w   = (FF * FF) / 4;
    cvt_h_kernel<<<(n4_act + 255) / 256, 256>>>(query, (__half*)pqh, n4_act);
    cvt_h_kernel<<<(n4_act + 255) / 256, 256>>>(key,   (__half*)pkh, n4_act);
    cvt_h_kernel<<<(n4_w + 255) / 256, 256>>>(Wq, (__half*)pwqh, n4_w);
    cvt_h_kernel<<<(n4_w + 255) / 256, 256>>>(Wk, (__half*)pwkh, n4_w);
    cvt_h_kernel<<<(n4_w + 255) / 256, 256>>>(Wo, (__half*)pwoh, n4_w);
    make_m_kernel<<<HH, 256>>>(We, Wr, Wc);

    // 1. q + k projections fused in one launch (fp16 out + chunk column sums)
    GemmArgs aq{(const __half*)pqh, (const __half*)pwqh, bq, (__half*)ppq, nullptr, (float*)pqc};
    GemmArgs ak{(const __half*)pkh, (const __half*)pwkh, bk, (__half*)ppk, nullptr, (float*)pkc};
    gemm_hmma<true><<<dim3(FF / Bb_N, MM / Bb_M, 2), 256, GEMM_SMEM>>>(aq, ak);

    // 2. exclusive scan over chunk sums
    scan_chunks_kernel<<<16, 256>>>();

    // 3. scan + l2norm -> fp16 qn/kn
    norm_kernel<<<256, 256>>>();

    // 4. x = qn@Me + kn@Mr + bc (batched HMMA)
    xgemm_kernel<<<dim3(SS / 128, BB * HH), 128, XG_SMEM>>>(bc);

    // 5. output projection (single-pass fp16 HMMA, fp32 out)
    GemmArgs ao{(const __half*)pxh, (const __half*)pwoh, bo, nullptr, out, nullptr};
    gemm_hmma<false><<<dim3(FF / Bb_N, MM / Bb_M, 1), 256, GEMM_SMEM>>>(ao, ao);
}

// round 8
// speedup vs baseline: 6.5870x; 1.1753x over previous
#include <cuda_runtime.h>
#include <cuda_fp16.h>
#include <cstdint>

// Problem constants
#define BB 4
#define SS 4096
#define FF 1024
#define HH 16
#define DKk 64
#define RR 32
#define CHUNK 128
#define NCH (SS / CHUNK)   // 32
#define MM (BB * SS)       // 16384

// GEMM tiling
#define Bb_M 128
#define Bb_N 128
#define NCHUNKS (FF / 32)          // 16 K-chunks of 32
#define STG 16384                  // A 8K | B 8K per stage
#define NSTAGES 4
#define GEMM_SMEM (NSTAGES * STG)  // 64 KB

// ---------------------------------------------------------------------------
// Scratch (device globals; no allocation allowed)
// ---------------------------------------------------------------------------
__device__ __half g_pq[MM * FF];   // projected q (fp16)
__device__ __half g_pk[MM * FF];   // projected k (fp16)
__device__ float g_qc[BB * NCH * FF];
__device__ float g_kc[BB * NCH * FF];
__device__ __half g_qh[MM * FF];   // fp16 query input
__device__ __half g_kh[MM * FF];   // fp16 key input
__device__ __half g_xh[MM * FF];   // pre-output activation (fp16)
__device__ __half g_wqh[FF * FF];
__device__ __half g_wkh[FF * FF];
__device__ __half g_woh[FF * FF];
__device__ __half g_meh[HH * DKk * DKk], g_mel[HH * DKk * DKk];
__device__ __half g_mrh[HH * DKk * DKk], g_mrl[HH * DKk * DKk];

struct GemmArgs {
    const __half* A;
    const __half* B;
    const float* bias;
    __half* Ch;     // used when HALFOUT
    float* Cf;      // used when !HALFOUT
    float* cs;      // optional per-chunk column sums
};

// ---------------------------------------------------------------------------
// PTX helpers (plain sm_80+ instructions: ldmatrix / mma.sync / cp.async)
// ---------------------------------------------------------------------------
__device__ __forceinline__ uint32_t smem_u32(const void* p) {
    uint32_t a;
    asm("{ .reg .u64 t; cvta.to.shared.u64 t, %1; cvt.u32.u64 %0, t; }" : "=r"(a) : "l"(p));
    return a;
}

__device__ __forceinline__ void cpasync16(uint32_t s, const void* g) {
    asm volatile("cp.async.cg.shared.global [%0], [%1], 16;" :: "r"(s), "l"(g));
}
__device__ __forceinline__ void cp_commit() {
    asm volatile("cp.async.commit_group;" ::: "memory");
}
template <int N>
__device__ __forceinline__ void cp_wait() {
    asm volatile("cp.async.wait_group %0;" :: "n"(N) : "memory");
}

__device__ __forceinline__ void ldsm4(uint32_t* r, uint32_t addr) {
    asm volatile("ldmatrix.sync.aligned.m8n8.x4.shared.b16 {%0,%1,%2,%3}, [%4];"
                 : "=r"(r[0]), "=r"(r[1]), "=r"(r[2]), "=r"(r[3]) : "r"(addr));
}

__device__ __forceinline__ void mma16816(float* c, const uint32_t* a, const uint32_t* b) {
    asm volatile(
        "mma.sync.aligned.m16n8k16.row.col.f32.f16.f16.f32 "
        "{%0,%1,%2,%3}, {%4,%5,%6,%7}, {%8,%9}, {%0,%1,%2,%3};"
        : "+f"(c[0]), "+f"(c[1]), "+f"(c[2]), "+f"(c[3])
        : "r"(a[0]), "r"(a[1]), "r"(a[2]), "r"(a[3]), "r"(b[0]), "r"(b[1]));
}

// ---------------------------------------------------------------------------
// All fp32->fp16 converts in ONE launch. Flat-grid job split (compile-time).
// ---------------------------------------------------------------------------
#define CV_ACT (MM * FF / 4 / 256)   // 16384 blocks per activation
#define CV_W   (FF * FF / 4 / 256)   // 1024 blocks per weight
__global__ void cvt_all_kernel(const float* __restrict__ q, const float* __restrict__ k,
                               const float* __restrict__ wq, const float* __restrict__ wk,
                               const float* __restrict__ wo)
{
    int bidx = blockIdx.x;
    const float* src; __half* dst; int i0;
    if (bidx < CV_ACT)                     { src = q;  dst = g_qh;  i0 = bidx; }
    else if (bidx < 2 * CV_ACT)            { src = k;  dst = g_kh;  i0 = bidx - CV_ACT; }
    else if (bidx < 2 * CV_ACT + CV_W)     { src = wq; dst = g_wqh; i0 = bidx - 2 * CV_ACT; }
    else if (bidx < 2 * CV_ACT + 2 * CV_W) { src = wk; dst = g_wkh; i0 = bidx - 2 * CV_ACT - CV_W; }
    else                                   { src = wo; dst = g_woh; i0 = bidx - 2 * CV_ACT - 2 * CV_W; }
    int i = i0 * 256 + threadIdx.x;
    float4 v = ((const float4*)src)[i];
    ((__half2*)dst)[2 * i]     = __floats2half2_rn(v.x, v.y);
    ((__half2*)dst)[2 * i + 1] = __floats2half2_rn(v.z, v.w);
}

// ---------------------------------------------------------------------------
// HMMA GEMM: C[m,n] = bias[n] + sum_k A[m,k]*B[n,k], single fp16 pass.
// 128x128 tile, K chunks of 32, 4-stage cp.async pipe, 2 CTAs/SM.
// blockIdx.z selects arg set (fused q/k launch). HALFOUT: write fp16.
// Optional colsum: per-128-row-chunk column sums of final C (incl bias).
// ---------------------------------------------------------------------------
template <bool HALFOUT>
__global__ __launch_bounds__(256, 2)
void gemm_hmma(GemmArgs g0, GemmArgs g1)
{
    const GemmArgs g = blockIdx.z ? g1 : g0;
    extern __shared__ char smem[];
    __shared__ float scs[2][128];
    const uint32_t sbase = smem_u32(smem);
    const int tid = threadIdx.x;
    const int wid = tid >> 5, lane = tid & 31;
    const int m0 = blockIdx.y * Bb_M;
    const int n0 = blockIdx.x * Bb_N;
    const int wm = (wid & 1) * 64;
    const int wn = (wid >> 1) * 32;

    const char* pA = (const char*)g.A + (size_t)m0 * (FF * 2);
    const char* pB = (const char*)g.B + (size_t)n0 * (FF * 2);

    const int lrow0 = tid >> 2;
    const int lseg = tid & 3;

    auto load_stage = [&](int c, int buf) {
        uint32_t sb = sbase + buf * STG;
        size_t kb = (size_t)c * 64;
#pragma unroll
        for (int i = 0; i < 2; i++) {
            int row = lrow0 + i * 64;
            uint32_t soff = row * 64 + ((lseg ^ ((row >> 1) & 3)) << 4);
            size_t goff = (size_t)row * (FF * 2) + kb + lseg * 16;
            cpasync16(sb + soff,        pA + goff);
            cpasync16(sb + 8192 + soff, pB + goff);
        }
        cp_commit();
    };

    float acc[4][4][4];
#pragma unroll
    for (int i = 0; i < 4; i++)
#pragma unroll
        for (int j = 0; j < 4; j++)
#pragma unroll
            for (int e = 0; e < 4; e++) acc[i][j][e] = 0.0f;

    int arow[4]; uint32_t aoffbase[4];
#pragma unroll
    for (int mf = 0; mf < 4; mf++) {
        arow[mf] = wm + mf * 16 + (lane & 15);
        aoffbase[mf] = arow[mf] * 64;
    }
    int brow[2];
#pragma unroll
    for (int ng = 0; ng < 2; ng++)
        brow[ng] = wn + ng * 16 + ((lane >> 4) << 3) + (lane & 7);

    load_stage(0, 0);
    load_stage(1, 1);
    load_stage(2, 2);

    for (int c = 0; c < NCHUNKS; c++) {
        if (c + 2 < NCHUNKS) cp_wait<2>();
        else if (c + 1 < NCHUNKS) cp_wait<1>();
        else cp_wait<0>();
        __syncthreads();
        if (c + 3 < NCHUNKS) load_stage(c + 3, (c + 3) % NSTAGES);

        uint32_t sb = sbase + (c % NSTAGES) * STG;
#pragma unroll
        for (int ks = 0; ks < 2; ks++) {
            uint32_t ah[4][4], bf[2][4];
#pragma unroll
            for (int mf = 0; mf < 4; mf++) {
                int seg = ks * 2 + (lane >> 4);
                uint32_t off = aoffbase[mf] + ((seg ^ ((arow[mf] >> 1) & 3)) << 4);
                ldsm4(ah[mf], sb + off);
            }
#pragma unroll
            for (int ng = 0; ng < 2; ng++) {
                int seg = ks * 2 + ((lane & 15) >> 3);
                uint32_t off = brow[ng] * 64 + ((seg ^ ((brow[ng] >> 1) & 3)) << 4);
                ldsm4(bf[ng], sb + 8192 + off);
            }
#pragma unroll
            for (int mf = 0; mf < 4; mf++)
#pragma unroll
                for (int nf = 0; nf < 4; nf++)
                    mma16816(acc[mf][nf], ah[mf], &bf[nf >> 1][(nf & 1) * 2]);
        }
    }

    // Epilogue: + bias, store (fp16 or fp32)
#pragma unroll
    for (int mf = 0; mf < 4; mf++) {
        int r0 = m0 + wm + mf * 16 + (lane >> 2);
#pragma unroll
        for (int nf = 0; nf < 4; nf++) {
            int col = n0 + wn + nf * 8 + (lane & 3) * 2;
            float bx = g.bias[col], by = g.bias[col + 1];
            float v00 = acc[mf][nf][0] + bx, v01 = acc[mf][nf][1] + by;
            float v10 = acc[mf][nf][2] + bx, v11 = acc[mf][nf][3] + by;
            if (HALFOUT) {
                *(__half2*)&g.Ch[(size_t)r0 * FF + col]       = __floats2half2_rn(v00, v01);
                *(__half2*)&g.Ch[(size_t)(r0 + 8) * FF + col] = __floats2half2_rn(v10, v11);
            } else {
                *(float2*)&g.Cf[(size_t)r0 * FF + col]       = make_float2(v00, v01);
                *(float2*)&g.Cf[(size_t)(r0 + 8) * FF + col] = make_float2(v10, v11);
            }
        }
    }

    // Optional: per-chunk column sums (this CTA's 128 rows == one (b,chunk))
    if (g.cs != nullptr) {
        float cs0[4], cs1[4];
#pragma unroll
        for (int nf = 0; nf < 4; nf++) {
            cs0[nf] = 0.f; cs1[nf] = 0.f;
#pragma unroll
            for (int mf = 0; mf < 4; mf++) {
                cs0[nf] += acc[mf][nf][0] + acc[mf][nf][2];
                cs1[nf] += acc[mf][nf][1] + acc[mf][nf][3];
            }
        }
#pragma unroll
        for (int o = 16; o >= 4; o >>= 1)
#pragma unroll
            for (int nf = 0; nf < 4; nf++) {
                cs0[nf] += __shfl_xor_sync(0xffffffffu, cs0[nf], o);
                cs1[nf] += __shfl_xor_sync(0xffffffffu, cs1[nf], o);
            }
        if (lane < 4) {
#pragma unroll
            for (int nf = 0; nf < 4; nf++) {
                scs[wid & 1][wn + nf * 8 + lane * 2]     = cs0[nf];
                scs[wid & 1][wn + nf * 8 + lane * 2 + 1] = cs1[nf];
            }
        }
        __syncthreads();
        if (tid < 128) {
            float tot = scs[0][tid] + scs[1][tid] + 128.0f * g.bias[n0 + tid];
            g.cs[(m0 >> 7) * FF + n0 + tid] = tot;
        }
    }
}

// ---------------------------------------------------------------------------
// Exclusive prefix over per-chunk sums (batched loads for MLP).
// ---------------------------------------------------------------------------
__global__ void scan_chunks_kernel()
{
    int t = blockIdx.x * blockDim.x + threadIdx.x;   // 0..4095
    int b = t >> 10;
    int col = t & 1023;
    int base = (b * NCH) * FF + col;
    float vq[NCH], vk[NCH];
#pragma unroll
    for (int ch = 0; ch < NCH; ch++) {
        vq[ch] = g_qc[base + ch * FF];
        vk[ch] = g_kc[base + ch * FF];
    }
    float aq = 0.f, ak = 0.f;
#pragma unroll
    for (int ch = 0; ch < NCH; ch++) {
        float tq = vq[ch]; vq[ch] = aq; aq += tq;
        float tk = vk[ch]; vk[ch] = ak; ak += tk;
    }
#pragma unroll
    for (int ch = 0; ch < NCH; ch++) {
        g_qc[base + ch * FF] = vq[ch];
        g_kc[base + ch * FF] = vk[ch];
    }
}

// ---------------------------------------------------------------------------
// Precompute per-head Me = We@Wc1^T, Mr = Wr@Wc2^T (stored [n][k], hi/lo fp16)
// ---------------------------------------------------------------------------
__global__ void make_m_kernel(const float* __restrict__ We, const float* __restrict__ Wr,
                              const float* __restrict__ Wc)
{
    int h = blockIdx.x;
    __shared__ float sWe[DKk * RR], sWr[DKk * RR], sWc[DKk * 2 * RR];
    for (int i = threadIdx.x; i < DKk * RR; i += 256) {
        sWe[i] = We[h * DKk * RR + i];
        sWr[i] = Wr[h * DKk * RR + i];
    }
    for (int i = threadIdx.x; i < DKk * 2 * RR; i += 256) sWc[i] = Wc[i];
    __syncthreads();
    for (int idx = threadIdx.x; idx < DKk * DKk; idx += 256) {
        int n = idx >> 6, k = idx & 63;
        float me = 0.f, mr = 0.f;
#pragma unroll
        for (int e = 0; e < RR; e++) {
            me += sWe[k * RR + e] * sWc[n * (2 * RR) + e];
            mr += sWr[k * RR + e] * sWc[n * (2 * RR) + RR + e];
        }
        __half meh = __float2half_rn(me);
        __half mrh = __float2half_rn(mr);
        g_meh[h * 4096 + idx] = meh;
        g_mel[h * 4096 + idx] = __float2half_rn(me - __half2float(meh));
        g_mrh[h * 4096 + idx] = mrh;
        g_mrl[h * 4096 + idx] = __float2half_rn(mr - __half2float(mrh));
    }
}

// ---------------------------------------------------------------------------
// Fused norm + xgemm: per (b,h,chunk=128 rows).
//   1. load pq/pk tile (fp16) + M matrices into smem
//   2. running-average + L2-normalize in smem (8 warps x 32-row sub-blocks,
//      sub-prefix fix-up through smem)
//   3. x = qn@(Meh+Mel) + kn@(Mrh+Mrl) + bc via HMMA; write fp16 x
// 256 threads. SMEM: sQ 16K | sK 16K | Meh/Mel/Mrh/Mrl 8K each = 64KB.
// Rows are 128B (64 fp16); swizzle seg ^= row&7.
// ---------------------------------------------------------------------------
#define XG_SMEM 65536
__global__ __launch_bounds__(256)
void xgemm_kernel(const float* __restrict__ bc)
{
    extern __shared__ char smem[];
    __shared__ float swsum[8][64];
    const uint32_t sbase = smem_u32(smem);
    const int tid = threadIdx.x;
    const int wid = tid >> 5, lane = tid & 31;
    const int ch = blockIdx.x;
    const int s0base = ch * 128;
    const int b = blockIdx.y >> 4;
    const int h = blockIdx.y & 15;

    // ---- load phase ----
    {
        const char* gq = (const char*)g_pq + (((size_t)(b * SS + s0base)) * FF + h * DKk) * 2;
        const char* gk = (const char*)g_pk + (((size_t)(b * SS + s0base)) * FF + h * DKk) * 2;
        int row = tid >> 1;                 // 0..127
        int sh = (tid & 1) * 4;
#pragma unroll
        for (int s = 0; s < 4; s++) {
            int seg = sh + s;
            uint32_t soff = row * 128 + ((seg ^ (row & 7)) << 4);
            size_t goff = (size_t)row * (FF * 2) + seg * 16;
            cpasync16(sbase + soff,         gq + goff);
            cpasync16(sbase + 16384 + soff, gk + goff);
        }
        const char* srcs[4] = {(const char*)(g_meh + h * 4096), (const char*)(g_mel + h * 4096),
                               (const char*)(g_mrh + h * 4096), (const char*)(g_mrl + h * 4096)};
#pragma unroll
        for (int j = 0; j < 8; j++) {
            int i = tid + j * 256;          // 0..2047
            int m = i >> 9;
            int r = (i >> 3) & 63;
            int seg = i & 7;
            uint32_t soff = r * 128 + ((seg ^ (r & 7)) << 4);
            cpasync16(sbase + 32768 + m * 8192 + soff, srcs[m] + r * 128 + seg * 16);
        }
        cp_commit();
    }
    cp_wait<0>();
    __syncthreads();

    // ---- norm phase ----
    {
        const int isK = wid >> 2;           // warps 0-3: q, 4-7: k
        const int blk = wid & 3;            // 32-row sub-block
        char* tb = smem + isK * 16384;
        const int segc = lane >> 2;         // seg of this lane's half2 (byte 4*lane)
        const int ib = (lane & 3) << 2;     // in-seg byte

        // sub-block column sums
        float s0 = 0.f, s1 = 0.f;
#pragma unroll 8
        for (int i = 0; i < 32; i++) {
            int r = blk * 32 + i;
            __half2 v = *(__half2*)(tb + r * 128 + ((segc ^ (r & 7)) << 4) + ib);
            float2 f = __half22float2(v);
            s0 += f.x; s1 += f.y;
        }
        swsum[wid][2 * lane] = s0;
        swsum[wid][2 * lane + 1] = s1;
        __syncthreads();

        // prefix = chunk prefix + lower sub-blocks
        const float* pc = isK ? g_kc : g_qc;
        int colg = (b * NCH + ch) * FF + h * DKk + 2 * lane;
        float p0 = pc[colg], p1 = pc[colg + 1];
        for (int w = isK * 4; w < wid; w++) {
            p0 += swsum[w][2 * lane];
            p1 += swsum[w][2 * lane + 1];
        }

        // serial scan + normalize (in place)
        int nbase = ch * CHUNK + blk * 32;
        for (int i = 0; i < 32; i++) {
            int r = blk * 32 + i;
            char* p = tb + r * 128 + ((segc ^ (r & 7)) << 4) + ib;
            float2 f = __half22float2(*(__half2*)p);
            p0 += f.x; p1 += f.y;
            float inv = 1.0f / (float)(nbase + i + 1);
            float a0 = p0 * inv, a1 = p1 * inv;
            float nrm = a0 * a0 + a1 * a1;
#pragma unroll
            for (int o = 16; o > 0; o >>= 1)
                nrm += __shfl_xor_sync(0xffffffffu, nrm, o);
            float rs = 1.0f / fmaxf(sqrtf(nrm), 1e-12f);
            *(__half2*)p = __floats2half2_rn(a0 * rs, a1 * rs);
        }
    }
    __syncthreads();

    // ---- mma phase: 8 warps, warp tile 16 rows x 64 cols ----
    const int wm = wid * 16;
    float acc[8][4];
#pragma unroll
    for (int j = 0; j < 8; j++)
#pragma unroll
        for (int e = 0; e < 4; e++) acc[j][e] = 0.0f;

#pragma unroll
    for (int part = 0; part < 2; part++) {
        uint32_t aBase = sbase + part * 16384;
        uint32_t hBase = sbase + 32768 + part * 16384;
        uint32_t lBase = hBase + 8192;
#pragma unroll
        for (int ks = 0; ks < 4; ks++) {
            uint32_t a[4], bhf[4][4], blf[4][4];
            {
                int arow = wm + (lane & 15);
                int seg = ks * 2 + (lane >> 4);
                ldsm4(a, aBase + arow * 128 + ((seg ^ (arow & 7)) << 4));
            }
#pragma unroll
            for (int ng = 0; ng < 4; ng++) {
                int brow = ng * 16 + ((lane >> 4) << 3) + (lane & 7);
                int seg = ks * 2 + ((lane & 15) >> 3);
                uint32_t off = brow * 128 + ((seg ^ (brow & 7)) << 4);
                ldsm4(bhf[ng], hBase + off);
                ldsm4(blf[ng], lBase + off);
            }
#pragma unroll
            for (int nf = 0; nf < 8; nf++) {
                mma16816(acc[nf], a, &bhf[nf >> 1][(nf & 1) * 2]);
                mma16816(acc[nf], a, &blf[nf >> 1][(nf & 1) * 2]);
            }
        }
    }

    // ---- epilogue ----
    {
        int s0r = s0base + wm + (lane >> 2);
#pragma unroll
        for (int nf = 0; nf < 8; nf++) {
            int col = nf * 8 + (lane & 3) * 2;
            float b0 = bc[col], b1 = bc[col + 1];
            size_t o0 = ((size_t)(b * SS + s0r)) * FF + h * DKk + col;
            size_t o1 = o0 + (size_t)8 * FF;
            *(__half2*)&g_xh[o0] = __floats2half2_rn(acc[nf][0] + b0, acc[nf][1] + b1);
            *(__half2*)&g_xh[o1] = __floats2half2_rn(acc[nf][2] + b0, acc[nf][3] + b1);
        }
    }
}

// ---------------------------------------------------------------------------
// Launch
// ---------------------------------------------------------------------------
extern "C" void kernel_launch(void* const* d_in, const int* in_sizes, int n_in,
                              void* d_out, int out_size)
{
    const float* query = (const float*)d_in[0];
    const float* key   = (const float*)d_in[1];
    const float* Wq = (const float*)d_in[4];
    const float* bq = (const float*)d_in[5];
    const float* Wk = (const float*)d_in[6];
    const float* bk = (const float*)d_in[7];
    const float* We = (const float*)d_in[10];
    const float* Wr = (const float*)d_in[11];
    const float* Wc = (const float*)d_in[13];
    const float* bc = (const float*)d_in[14];
    const float* Wo = (const float*)d_in[15];
    const float* bo = (const float*)d_in[16];
    float* out = (float*)d_out;

    void *ppq, *ppk, *pqc, *pkc, *pqh, *pkh, *pxh;
    void *pwqh, *pwkh, *pwoh;
    cudaGetSymbolAddress(&ppq, g_pq);
    cudaGetSymbolAddress(&ppk, g_pk);
    cudaGetSymbolAddress(&pqc, g_qc);
    cudaGetSymbolAddress(&pkc, g_kc);
    cudaGetSymbolAddress(&pqh, g_qh);
    cudaGetSymbolAddress(&pkh, g_kh);
    cudaGetSymbolAddress(&pxh, g_xh);
    cudaGetSymbolAddress(&pwqh, g_wqh);
    cudaGetSymbolAddress(&pwkh, g_wkh);
    cudaGetSymbolAddress(&pwoh, g_woh);

    cudaFuncSetAttribute(gemm_hmma<true>,  cudaFuncAttributeMaxDynamicSharedMemorySize, GEMM_SMEM);
    cudaFuncSetAttribute(gemm_hmma<false>, cudaFuncAttributeMaxDynamicSharedMemorySize, GEMM_SMEM);
    cudaFuncSetAttribute(xgemm_kernel,     cudaFuncAttributeMaxDynamicSharedMemorySize, XG_SMEM);

    // 0. all converts in one launch + M precompute
    cvt_all_kernel<<<2 * CV_ACT + 3 * CV_W, 256>>>(query, key, Wq, Wk, Wo);
    make_m_kernel<<<HH, 256>>>(We, Wr, Wc);

    // 1. q + k projections fused in one launch (fp16 out + chunk column sums)
    GemmArgs aq{(const __half*)pqh, (const __half*)pwqh, bq, (__half*)ppq, nullptr, (float*)pqc};
    GemmArgs ak{(const __half*)pkh, (const __half*)pwkh, bk, (__half*)ppk, nullptr, (float*)pkc};
    gemm_hmma<true><<<dim3(FF / Bb_N, MM / Bb_M, 2), 256, GEMM_SMEM>>>(aq, ak);

    // 2. exclusive scan over chunk sums
    scan_chunks_kernel<<<16, 256>>>();

    // 3. fused norm + x = qn@Me + kn@Mr + bc (batched HMMA)
    xgemm_kernel<<<dim3(NCH, BB * HH), 256, XG_SMEM>>>(bc);

    // 4. output projection (single-pass fp16 HMMA, fp32 out)
    GemmArgs ao{(const __half*)pxh, (const __half*)pwoh, bo, nullptr, out, nullptr};
    gemm_hmma<false><<<dim3(FF / Bb_N, MM / Bb_M, 1), 256, GEMM_SMEM>>>(ao, ao);
}